// round 8
// baseline (speedup 1.0000x reference)
#include <cuda_runtime.h>
#include <cuda_bf16.h>
#include <cstdint>
#include <math.h>

#define T_TOK 1024
#define HID   2048
#define IMID  1024
#define NEXP  16
#define TOPK  6
#define NPAIR (T_TOK * TOPK)
#define ISH   2048
#define RSCALE 2.5f

// ---------------- scratch ----------------
__device__ float g_hb [(size_t)NPAIR * IMID];
__device__ float g_hs [(size_t)T_TOK * ISH];
__device__ float g_part[(size_t)NPAIR * HID];
__device__ float g_so [(size_t)T_TOK * HID];
__device__ int   g_cnt [NEXP];
__device__ int   g_list[NEXP * T_TOK];
__device__ float g_tw  [T_TOK * TOPK];

// ---------------- helpers ----------------
__device__ __forceinline__ uint32_t smem_u32(const void* p) {
    uint32_t a;
    asm("{ .reg .u64 t; cvta.to.shared.u64 t, %1; cvt.u32.u64 %0, t; }" : "=r"(a) : "l"(p));
    return a;
}
__device__ __forceinline__ float silu_f(float x) { return x / (1.f + expf(-x)); }

#define LDSM4(r, addr) \
    asm volatile("ldmatrix.sync.aligned.m8n8.x4.shared.b16 {%0,%1,%2,%3}, [%4];" \
        : "=r"((r)[0]), "=r"((r)[1]), "=r"((r)[2]), "=r"((r)[3]) : "r"(addr))

__device__ __forceinline__ void mma_bf16(float* c, const uint32_t* a, const uint32_t* b) {
    asm volatile(
        "mma.sync.aligned.m16n8k16.row.col.f32.bf16.bf16.f32 "
        "{%0,%1,%2,%3}, {%4,%5,%6,%7}, {%8,%9}, {%0,%1,%2,%3};"
        : "+f"(c[0]), "+f"(c[1]), "+f"(c[2]), "+f"(c[3])
        : "r"(a[0]), "r"(a[1]), "r"(a[2]), "r"(a[3]), "r"(b[0]), "r"(b[1]));
}

// 640 threads: 16 consumer warps + 4 producer warps
#define NTHR 640
#define NCONS 512
#define BAR_SYNC(id)   asm volatile("bar.sync %0, %1;"   :: "r"(id), "r"(NTHR) : "memory")
#define BAR_ARRIVE(id) asm volatile("bar.arrive %0, %1;" :: "r"(id), "r"(NTHR) : "memory")
// ids: 1 = full0, 2 = full1, 3 = empty0, 4 = empty1

// ---------------- router ----------------
__global__ void zero_cnt_kernel(int* cnt) { if (threadIdx.x < NEXP) cnt[threadIdx.x] = 0; }

__global__ void __launch_bounds__(256)
router_kernel(const float* __restrict__ X, const float* __restrict__ gw,
              const float* __restrict__ bias,
              int* __restrict__ cnt, int* __restrict__ list, float* __restrict__ tw)
{
    int t = blockIdx.x;
    __shared__ float red[NEXP * 256];
    float acc[NEXP];
#pragma unroll
    for (int e = 0; e < NEXP; e++) acc[e] = 0.f;
    const float* x = X + (size_t)t * HID;
    for (int h = threadIdx.x; h < HID; h += 256) {
        float xv = x[h];
#pragma unroll
        for (int e = 0; e < NEXP; e++) acc[e] += xv * gw[e * HID + h];
    }
#pragma unroll
    for (int e = 0; e < NEXP; e++) red[e * 256 + threadIdx.x] = acc[e];
    __syncthreads();
    for (int s = 128; s > 0; s >>= 1) {
        if (threadIdx.x < s) {
#pragma unroll
            for (int e = 0; e < NEXP; e++)
                red[e * 256 + threadIdx.x] += red[e * 256 + threadIdx.x + s];
        }
        __syncthreads();
    }
    if (threadIdx.x == 0) {
        float sc[NEXP], ch[NEXP];
#pragma unroll
        for (int e = 0; e < NEXP; e++) {
            float l = red[e * 256];
            float s = 1.f / (1.f + expf(-l));
            sc[e] = s; ch[e] = s + bias[e];
        }
        bool used[NEXP];
#pragma unroll
        for (int e = 0; e < NEXP; e++) used[e] = false;
        int sel[TOPK]; float wsum = 0.f;
        for (int k = 0; k < TOPK; k++) {
            float best = -1e30f; int bi = 0;
            for (int e = 0; e < NEXP; e++)
                if (!used[e] && ch[e] > best) { best = ch[e]; bi = e; }
            used[bi] = true; sel[k] = bi; wsum += sc[bi];
        }
        float inv = RSCALE / wsum;
        for (int k = 0; k < TOPK; k++) {
            tw[t * TOPK + k] = sc[sel[k]] * inv;
            int pos = atomicAdd(&cnt[sel[k]], 1);
            list[sel[k] * T_TOK + pos] = t * TOPK + k;
        }
    }
}

// ---------------- warp-specialized split-bf16 MMA GEMM ----------------
// 16 consumer warps (4M x 4N, 32x32 each) + 4 producer warps, 2-stage SMEM pipe.
#define BM 128
#define BROWS 128
#define TILE_B 16384
#define STAGE_B 65536

template<bool FUSED>
__global__ void __launch_bounds__(NTHR, 1)
mma_gemm(const float* __restrict__ A,
         const float* __restrict__ Bbase, long long bStride,
         float* __restrict__ C, int cStride, int upOff,
         int Mfixed, const int* __restrict__ cnt, int K,
         const int* __restrict__ list, int adiv)
{
    const int e = blockIdx.z;
    const int M = cnt ? cnt[e] : Mfixed;
    const int m0 = blockIdx.y * BM;
    if (m0 >= M) return;
    const int n0 = blockIdx.x;
    const float* B = Bbase + (size_t)e * bStride;
    const int* lst = list ? (list + e * T_TOK) : nullptr;

    extern __shared__ char dynraw[];
    char* dyn = (char*)(((uintptr_t)dynraw + 1023) & ~(uintptr_t)1023);
    const uint32_t dynu = smem_u32(dyn);

    __shared__ int s_aOff[BM];
    __shared__ int s_cRow[BM];
    __shared__ int s_bRow[BROWS];

    const int tid = threadIdx.x;
    const int lane = tid & 31;
    const int warp = tid >> 5;

    if (tid < BM) {
        int r = m0 + tid; if (r > M - 1) r = M - 1;
        int pr = lst ? lst[r] : r;
        s_cRow[tid] = pr;
        s_aOff[tid] = (lst ? pr / adiv : pr) * K;
        int bj;
        if (FUSED) bj = (tid >> 1) + n0 * 64 + ((tid & 1) ? upOff : 0);
        else       bj = n0 * BROWS + tid;
        s_bRow[tid] = bj;
    }
    __syncthreads();

    const int NC = K >> 6;

    if (warp >= 16) {
        // ================= PRODUCER (warps 16..19, 128 threads) =================
        const int ptid = tid - NCONS;
        const int pr8 = ptid >> 4;          // base row 0..7
        const int pc4 = ptid & 15;          // float4 column

        for (int i = 0; i < NC; i++) {
            const int s = i & 1;
            if (i >= 2) BAR_SYNC(3 + s);            // wait empty
            char* sb = dyn + s * STAGE_B;
            const int k0 = i << 6;

            float4 va[8], vb[8];

#define LOADG(gidx, vv)                                                          \
            _Pragma("unroll")                                                    \
            for (int j = 0; j < 8; j++) {                                        \
                const int slot = (gidx) * 8 + j;                                 \
                const int row = pr8 + 8 * (slot & 15);                           \
                const int off = (slot < 16) ? s_aOff[row]                        \
                                            : (s_bRow[row] * K);                 \
                (vv)[j] = *(const float4*)(((slot < 16) ? A : B) + off +         \
                                           pc4 * 4 + k0);                        \
            }
#define STOREG(gidx, vv)                                                         \
            _Pragma("unroll")                                                    \
            for (int j = 0; j < 8; j++) {                                        \
                const int slot = (gidx) * 8 + j;                                 \
                const int row = pr8 + 8 * (slot & 15);                           \
                uint32_t swz = (uint32_t)(row * 128 + pc4 * 8);                  \
                swz ^= (uint32_t)(row & 7) << 4;                                 \
                uint32_t o = ((slot < 16) ? 0u : 2u * TILE_B) + swz;             \
                float4 x = (vv)[j];                                              \
                __nv_bfloat162 h01 = __floats2bfloat162_rn(x.x, x.y);            \
                __nv_bfloat162 h23 = __floats2bfloat162_rn(x.z, x.w);            \
                float r0 = x.x - __bfloat162float(h01.x);                        \
                float r1 = x.y - __bfloat162float(h01.y);                        \
                float r2 = x.z - __bfloat162float(h23.x);                        \
                float r3 = x.w - __bfloat162float(h23.y);                        \
                __nv_bfloat162 l01 = __floats2bfloat162_rn(r0, r1);              \
                __nv_bfloat162 l23 = __floats2bfloat162_rn(r2, r3);              \
                uint2 hw, lw;                                                    \
                hw.x = *(uint32_t*)&h01; hw.y = *(uint32_t*)&h23;                \
                lw.x = *(uint32_t*)&l01; lw.y = *(uint32_t*)&l23;                \
                *(uint2*)(sb + o) = hw;                                          \
                *(uint2*)(sb + o + TILE_B) = lw;                                 \
            }

            LOADG(0, va)
            LOADG(1, vb) STOREG(0, va)
            LOADG(2, va) STOREG(1, vb)
            LOADG(3, vb) STOREG(2, va)
            STOREG(3, vb)
#undef LOADG
#undef STOREG
            BAR_ARRIVE(1 + s);                      // signal full
        }
        return;
    }

    // ================= CONSUMER (warps 0..15; 4M x 4N, 32x32 tile) =================
    const int wm = warp & 3;
    const int wn = warp >> 2;
    const int aRow0 = wm * 32 + (lane & 7) + ((lane >> 3) & 1) * 8;
    const uint32_t aHi16 = ((lane >> 4) & 1) * 16;
    const uint32_t xorA = (uint32_t)(aRow0 & 7) << 4;
    const int bRow0 = wn * 32 + (lane & 7) + ((lane >> 4) & 1) * 8;
    const uint32_t bHi16 = ((lane >> 3) & 1) * 16;
    const uint32_t xorB = (uint32_t)(bRow0 & 7) << 4;

    float acc[2][4][4];
#pragma unroll
    for (int a = 0; a < 2; a++)
#pragma unroll
        for (int b = 0; b < 4; b++)
#pragma unroll
            for (int c = 0; c < 4; c++) acc[a][b][c] = 0.f;

    for (int i = 0; i < NC; i++) {
        const int s = i & 1;
        BAR_SYNC(1 + s);                            // wait full
        const uint32_t su = dynu + s * STAGE_B;
#pragma unroll
        for (int ks = 0; ks < 4; ks++) {
            uint32_t aH[8], aL[8], bH[8], bL[8];
#pragma unroll
            for (int g = 0; g < 2; g++) {
                uint32_t ao = su + (uint32_t)(aRow0 + g * 16) * 128 +
                              (((uint32_t)ks * 32 + aHi16) ^ xorA);
                LDSM4(&aH[g * 4], ao);
                LDSM4(&aL[g * 4], ao + TILE_B);
            }
#pragma unroll
            for (int q = 0; q < 2; q++) {
                uint32_t bo = su + 2 * TILE_B +
                              (uint32_t)(bRow0 + q * 16) * 128 +
                              (((uint32_t)ks * 32 + bHi16) ^ xorB);
                LDSM4(&bH[q * 4], bo);
                LDSM4(&bL[q * 4], bo + TILE_B);
            }
            // pass-reordered: 8 independent MMAs per pass
#pragma unroll
            for (int mi = 0; mi < 2; mi++)
#pragma unroll
                for (int ni = 0; ni < 4; ni++)
                    mma_bf16(acc[mi][ni], &aH[mi * 4],
                             &bH[(ni >> 1) * 4 + (ni & 1) * 2]);
#pragma unroll
            for (int mi = 0; mi < 2; mi++)
#pragma unroll
                for (int ni = 0; ni < 4; ni++)
                    mma_bf16(acc[mi][ni], &aH[mi * 4],
                             &bL[(ni >> 1) * 4 + (ni & 1) * 2]);
#pragma unroll
            for (int mi = 0; mi < 2; mi++)
#pragma unroll
                for (int ni = 0; ni < 4; ni++)
                    mma_bf16(acc[mi][ni], &aL[mi * 4],
                             &bH[(ni >> 1) * 4 + (ni & 1) * 2]);
        }
        if (i + 2 < NC) BAR_ARRIVE(3 + s);          // signal empty
    }

    // ---- epilogue ----
#pragma unroll
    for (int mi = 0; mi < 2; mi++) {
#pragma unroll
        for (int nt = 0; nt < 4; nt++) {
            const float* c = acc[mi][nt];
            int rl0 = wm * 32 + mi * 16 + (lane >> 2);
            int rl1 = rl0 + 8;
            if (FUSED) {
                int col = n0 * 64 + wn * 16 + nt * 4 + (lane & 3);
                if (m0 + rl0 < M)
                    C[(size_t)s_cRow[rl0] * cStride + col] = silu_f(c[0]) * c[1];
                if (m0 + rl1 < M)
                    C[(size_t)s_cRow[rl1] * cStride + col] = silu_f(c[2]) * c[3];
            } else {
                int col = n0 * BROWS + wn * 32 + nt * 8 + 2 * (lane & 3);
                if (m0 + rl0 < M) {
                    float2 o; o.x = c[0]; o.y = c[1];
                    *(float2*)(C + (size_t)s_cRow[rl0] * cStride + col) = o;
                }
                if (m0 + rl1 < M) {
                    float2 o; o.x = c[2]; o.y = c[3];
                    *(float2*)(C + (size_t)s_cRow[rl1] * cStride + col) = o;
                }
            }
        }
    }
}

// ---------------- combine ----------------
__global__ void combine_kernel(float* __restrict__ out,
                               const float* __restrict__ so,
                               const float* __restrict__ part,
                               const float* __restrict__ tw)
{
    int idx = blockIdx.x * blockDim.x + threadIdx.x;
    if (idx >= T_TOK * HID / 4) return;
    int t = idx / (HID / 4);
    int c = (idx % (HID / 4)) * 4;
    float4 acc = *(const float4*)(so + (size_t)t * HID + c);
#pragma unroll
    for (int s = 0; s < TOPK; s++) {
        float w = tw[t * TOPK + s];
        float4 pv = *(const float4*)(part + (size_t)(t * TOPK + s) * HID + c);
        acc.x = fmaf(w, pv.x, acc.x);
        acc.y = fmaf(w, pv.y, acc.y);
        acc.z = fmaf(w, pv.z, acc.z);
        acc.w = fmaf(w, pv.w, acc.w);
    }
    *(float4*)(out + (size_t)t * HID + c) = acc;
}

// ---------------- launch ----------------
extern "C" void kernel_launch(void* const* d_in, const int* in_sizes, int n_in,
                              void* d_out, int out_size)
{
    (void)in_sizes; (void)n_in; (void)out_size;
    const float* X    = (const float*)d_in[0];
    const float* gw   = (const float*)d_in[1];
    const float* bias = (const float*)d_in[2];
    const float* w1   = (const float*)d_in[3];
    const float* w2   = (const float*)d_in[4];
    const float* sw1  = (const float*)d_in[5];
    const float* sw2  = (const float*)d_in[6];
    float* out = (float*)d_out;

    float *p_hb, *p_hs, *p_part, *p_so, *p_tw;
    int *p_cnt, *p_list;
    cudaGetSymbolAddress((void**)&p_hb,   g_hb);
    cudaGetSymbolAddress((void**)&p_hs,   g_hs);
    cudaGetSymbolAddress((void**)&p_part, g_part);
    cudaGetSymbolAddress((void**)&p_so,   g_so);
    cudaGetSymbolAddress((void**)&p_tw,   g_tw);
    cudaGetSymbolAddress((void**)&p_cnt,  g_cnt);
    cudaGetSymbolAddress((void**)&p_list, g_list);

    const size_t dynsm = 2 * STAGE_B + 1024;
    cudaFuncSetAttribute(mma_gemm<true>,  cudaFuncAttributeMaxDynamicSharedMemorySize, (int)dynsm);
    cudaFuncSetAttribute(mma_gemm<false>, cudaFuncAttributeMaxDynamicSharedMemorySize, (int)dynsm);

    // 1. router
    zero_cnt_kernel<<<1, 32>>>(p_cnt);
    router_kernel<<<T_TOK, 256>>>(X, gw, bias, p_cnt, p_list, p_tw);

    // 2. shared expert
    mma_gemm<true><<<dim3(ISH / 64, T_TOK / BM, 1), NTHR, dynsm>>>(
        X, sw1, 0, p_hs, ISH, ISH, T_TOK, nullptr, HID, nullptr, 1);
    mma_gemm<false><<<dim3(HID / BROWS, T_TOK / BM, 1), NTHR, dynsm>>>(
        p_hs, sw2, 0, p_so, HID, 0, T_TOK, nullptr, ISH, nullptr, 1);

    // 3. routed experts
    mma_gemm<true><<<dim3(IMID / 64, 8, NEXP), NTHR, dynsm>>>(
        X, w1, (long long)(2 * IMID) * HID, p_hb, IMID, IMID,
        0, p_cnt, HID, p_list, TOPK);
    mma_gemm<false><<<dim3(HID / BROWS, 8, NEXP), NTHR, dynsm>>>(
        p_hb, w2, (long long)HID * IMID, p_part, HID, 0,
        0, p_cnt, IMID, p_list, 1);

    // 4. combine
    combine_kernel<<<(T_TOK * HID / 4 + 255) / 256, 256>>>(out, p_so, p_part, p_tw);
}

// round 10
// speedup vs baseline: 1.0063x; 1.0063x over previous
#include <cuda_runtime.h>
#include <cuda_bf16.h>
#include <cstdint>
#include <math.h>

#define T_TOK 1024
#define HID   2048
#define IMID  1024
#define NEXP  16
#define TOPK  6
#define NPAIR (T_TOK * TOPK)
#define ISH   2048
#define RSCALE 2.5f

// ---------------- scratch ----------------
__device__ float g_hb [(size_t)NPAIR * IMID];
__device__ float g_hs [(size_t)T_TOK * ISH];
__device__ float g_part[(size_t)NPAIR * HID];
__device__ float g_so [(size_t)T_TOK * HID];
__device__ int   g_cnt [NEXP];
__device__ int   g_list[NEXP * T_TOK];
__device__ float g_tw  [T_TOK * TOPK];

// ---------------- helpers ----------------
__device__ __forceinline__ uint32_t smem_u32(const void* p) {
    uint32_t a;
    asm("{ .reg .u64 t; cvta.to.shared.u64 t, %1; cvt.u32.u64 %0, t; }" : "=r"(a) : "l"(p));
    return a;
}
__device__ __forceinline__ float silu_f(float x) { return x / (1.f + expf(-x)); }

#define LDSM4(r, addr) \
    asm volatile("ldmatrix.sync.aligned.m8n8.x4.shared.b16 {%0,%1,%2,%3}, [%4];" \
        : "=r"((r)[0]), "=r"((r)[1]), "=r"((r)[2]), "=r"((r)[3]) : "r"(addr))

__device__ __forceinline__ void mma_bf16(float* c, const uint32_t* a, const uint32_t* b) {
    asm volatile(
        "mma.sync.aligned.m16n8k16.row.col.f32.bf16.bf16.f32 "
        "{%0,%1,%2,%3}, {%4,%5,%6,%7}, {%8,%9}, {%0,%1,%2,%3};"
        : "+f"(c[0]), "+f"(c[1]), "+f"(c[2]), "+f"(c[3])
        : "r"(a[0]), "r"(a[1]), "r"(a[2]), "r"(a[3]), "r"(b[0]), "r"(b[1]));
}

// 256 threads: 4 consumer warps (64x64 tiles) + 4 producer warps
#define NTHR 256
#define NCONS 128
#define NSTAGE 3
#define BAR_SYNC(id)   asm volatile("bar.sync %0, %1;"   :: "r"(id), "r"(NTHR) : "memory")
#define BAR_ARRIVE(id) asm volatile("bar.arrive %0, %1;" :: "r"(id), "r"(NTHR) : "memory")
// ids: 1..3 = full[stage], 4..6 = empty[stage]

// ---------------- router ----------------
__global__ void zero_cnt_kernel(int* cnt) { if (threadIdx.x < NEXP) cnt[threadIdx.x] = 0; }

__global__ void __launch_bounds__(256)
router_kernel(const float* __restrict__ X, const float* __restrict__ gw,
              const float* __restrict__ bias,
              int* __restrict__ cnt, int* __restrict__ list, float* __restrict__ tw)
{
    int t = blockIdx.x;
    __shared__ float red[NEXP * 256];
    float acc[NEXP];
#pragma unroll
    for (int e = 0; e < NEXP; e++) acc[e] = 0.f;
    const float* x = X + (size_t)t * HID;
    for (int h = threadIdx.x; h < HID; h += 256) {
        float xv = x[h];
#pragma unroll
        for (int e = 0; e < NEXP; e++) acc[e] += xv * gw[e * HID + h];
    }
#pragma unroll
    for (int e = 0; e < NEXP; e++) red[e * 256 + threadIdx.x] = acc[e];
    __syncthreads();
    for (int s = 128; s > 0; s >>= 1) {
        if (threadIdx.x < s) {
#pragma unroll
            for (int e = 0; e < NEXP; e++)
                red[e * 256 + threadIdx.x] += red[e * 256 + threadIdx.x + s];
        }
        __syncthreads();
    }
    if (threadIdx.x == 0) {
        float sc[NEXP], ch[NEXP];
#pragma unroll
        for (int e = 0; e < NEXP; e++) {
            float l = red[e * 256];
            float s = 1.f / (1.f + expf(-l));
            sc[e] = s; ch[e] = s + bias[e];
        }
        bool used[NEXP];
#pragma unroll
        for (int e = 0; e < NEXP; e++) used[e] = false;
        int sel[TOPK]; float wsum = 0.f;
        for (int k = 0; k < TOPK; k++) {
            float best = -1e30f; int bi = 0;
            for (int e = 0; e < NEXP; e++)
                if (!used[e] && ch[e] > best) { best = ch[e]; bi = e; }
            used[bi] = true; sel[k] = bi; wsum += sc[bi];
        }
        float inv = RSCALE / wsum;
        for (int k = 0; k < TOPK; k++) {
            tw[t * TOPK + k] = sc[sel[k]] * inv;
            int pos = atomicAdd(&cnt[sel[k]], 1);
            list[sel[k] * T_TOK + pos] = t * TOPK + k;
        }
    }
}

// ---------------- warp-specialized split-bf16 MMA GEMM ----------------
// 4 consumer warps (2M x 2N, 64x64 each; high fragment reuse -> low LDSM traffic)
// + 4 producer warps (LDG -> hi/lo cvt -> STS), 3-stage SMEM pipe.
#define BM 128
#define BROWS 128
#define TILE_B 16384
#define STAGE_B 65536

template<bool FUSED>
__global__ void __launch_bounds__(NTHR, 1)
mma_gemm(const float* __restrict__ A,
         const float* __restrict__ Bbase, long long bStride,
         float* __restrict__ C, int cStride, int upOff,
         int Mfixed, const int* __restrict__ cnt, int K,
         const int* __restrict__ list, int adiv)
{
    const int e = blockIdx.z;
    const int M = cnt ? cnt[e] : Mfixed;
    const int m0 = blockIdx.y * BM;
    if (m0 >= M) return;
    const int n0 = blockIdx.x;
    const float* B = Bbase + (size_t)e * bStride;
    const int* lst = list ? (list + e * T_TOK) : nullptr;

    extern __shared__ char dynraw[];
    char* dyn = (char*)(((uintptr_t)dynraw + 1023) & ~(uintptr_t)1023);
    const uint32_t dynu = smem_u32(dyn);

    __shared__ int s_aOff[BM];
    __shared__ int s_cRow[BM];
    __shared__ int s_bRow[BROWS];

    const int tid = threadIdx.x;
    const int lane = tid & 31;
    const int warp = tid >> 5;

    if (tid < BM) {
        int r = m0 + tid; if (r > M - 1) r = M - 1;
        int pr = lst ? lst[r] : r;
        s_cRow[tid] = pr;
        s_aOff[tid] = (lst ? pr / adiv : pr) * K;
        int bj;
        if (FUSED) bj = (tid >> 1) + n0 * 64 + ((tid & 1) ? upOff : 0);
        else       bj = n0 * BROWS + tid;
        s_bRow[tid] = bj;
    }
    __syncthreads();

    const int NC = K >> 6;

    if (warp >= 4) {
        // ================= PRODUCER (warps 4..7, 128 threads) =================
        const int ptid = tid - NCONS;
        const int pr8 = ptid >> 4;          // base row 0..7
        const int pc4 = ptid & 15;          // float4 column

        for (int i = 0; i < NC; i++) {
            const int s = i % NSTAGE;
            if (i >= NSTAGE) BAR_SYNC(4 + s);       // wait empty
            char* sb = dyn + s * STAGE_B;
            const int k0 = i << 6;

            float4 va[8], vb[8];

#define LOADG(gidx, vv)                                                          \
            _Pragma("unroll")                                                    \
            for (int j = 0; j < 8; j++) {                                        \
                const int slot = (gidx) * 8 + j;                                 \
                const int row = pr8 + 8 * (slot & 15);                           \
                const int off = (slot < 16) ? s_aOff[row]                        \
                                            : (s_bRow[row] * K);                 \
                (vv)[j] = *(const float4*)(((slot < 16) ? A : B) + off +         \
                                           pc4 * 4 + k0);                        \
            }
#define STOREG(gidx, vv)                                                         \
            _Pragma("unroll")                                                    \
            for (int j = 0; j < 8; j++) {                                        \
                const int slot = (gidx) * 8 + j;                                 \
                const int row = pr8 + 8 * (slot & 15);                           \
                uint32_t swz = (uint32_t)(row * 128 + pc4 * 8);                  \
                swz ^= (uint32_t)(row & 7) << 4;                                 \
                uint32_t o = ((slot < 16) ? 0u : 2u * TILE_B) + swz;             \
                float4 x = (vv)[j];                                              \
                __nv_bfloat162 h01 = __floats2bfloat162_rn(x.x, x.y);            \
                __nv_bfloat162 h23 = __floats2bfloat162_rn(x.z, x.w);            \
                float r0 = x.x - __bfloat162float(h01.x);                        \
                float r1 = x.y - __bfloat162float(h01.y);                        \
                float r2 = x.z - __bfloat162float(h23.x);                        \
                float r3 = x.w - __bfloat162float(h23.y);                        \
                __nv_bfloat162 l01 = __floats2bfloat162_rn(r0, r1);              \
                __nv_bfloat162 l23 = __floats2bfloat162_rn(r2, r3);              \
                uint2 hw, lw;                                                    \
                hw.x = *(uint32_t*)&h01; hw.y = *(uint32_t*)&h23;                \
                lw.x = *(uint32_t*)&l01; lw.y = *(uint32_t*)&l23;                \
                *(uint2*)(sb + o) = hw;                                          \
                *(uint2*)(sb + o + TILE_B) = lw;                                 \
            }

            LOADG(0, va)
            LOADG(1, vb) STOREG(0, va)
            LOADG(2, va) STOREG(1, vb)
            LOADG(3, vb) STOREG(2, va)
            STOREG(3, vb)
#undef LOADG
#undef STOREG
            BAR_ARRIVE(1 + s);                      // signal full
        }
        return;
    }

    // ================= CONSUMER (warps 0..3; 2M x 2N, 64x64 tile each) =================
    const int wm = warp & 1;
    const int wn = (warp >> 1) & 1;
    const int aRow0 = wm * 64 + (lane & 7) + ((lane >> 3) & 1) * 8;
    const uint32_t aHi16 = ((lane >> 4) & 1) * 16;
    const uint32_t xorA = (uint32_t)(aRow0 & 7) << 4;
    const int bRow0 = wn * 64 + (lane & 7) + ((lane >> 4) & 1) * 8;
    const uint32_t bHi16 = ((lane >> 3) & 1) * 16;
    const uint32_t xorB = (uint32_t)(bRow0 & 7) << 4;

    float acc[4][8][4];   // [m16 tile][n8 tile][frag]
#pragma unroll
    for (int a = 0; a < 4; a++)
#pragma unroll
        for (int b = 0; b < 8; b++)
#pragma unroll
            for (int c = 0; c < 4; c++) acc[a][b][c] = 0.f;

    for (int i = 0; i < NC; i++) {
        const int s = i % NSTAGE;
        BAR_SYNC(1 + s);                            // wait full
        const uint32_t su = dynu + s * STAGE_B;
#pragma unroll
        for (int ks = 0; ks < 4; ks++) {
            uint32_t aH[16], aL[16];
#pragma unroll
            for (int g = 0; g < 4; g++) {
                uint32_t ao = su + (uint32_t)(aRow0 + g * 16) * 128 +
                              (((uint32_t)ks * 32 + aHi16) ^ xorA);
                LDSM4(&aH[g * 4], ao);
                LDSM4(&aL[g * 4], ao + TILE_B);
            }
#pragma unroll
            for (int q = 0; q < 4; q++) {
                uint32_t bH[4], bL[4];
                uint32_t bo = su + 2 * TILE_B +
                              (uint32_t)(bRow0 + q * 16) * 128 +
                              (((uint32_t)ks * 32 + bHi16) ^ xorB);
                LDSM4(bH, bo);
                LDSM4(bL, bo + TILE_B);
                // 3 passes; 8 independent MMAs per pass
#pragma unroll
                for (int mi = 0; mi < 4; mi++) {
                    mma_bf16(acc[mi][q * 2 + 0], &aH[mi * 4], &bH[0]);
                    mma_bf16(acc[mi][q * 2 + 1], &aH[mi * 4], &bH[2]);
                }
#pragma unroll
                for (int mi = 0; mi < 4; mi++) {
                    mma_bf16(acc[mi][q * 2 + 0], &aH[mi * 4], &bL[0]);
                    mma_bf16(acc[mi][q * 2 + 1], &aH[mi * 4], &bL[2]);
                }
#pragma unroll
                for (int mi = 0; mi < 4; mi++) {
                    mma_bf16(acc[mi][q * 2 + 0], &aL[mi * 4], &bH[0]);
                    mma_bf16(acc[mi][q * 2 + 1], &aL[mi * 4], &bH[2]);
                }
            }
        }
        if (i + NSTAGE < NC) BAR_ARRIVE(4 + s);     // signal empty
    }

    // ---- epilogue ----
#pragma unroll
    for (int mi = 0; mi < 4; mi++) {
#pragma unroll
        for (int nt = 0; nt < 8; nt++) {
            const float* c = acc[mi][nt];
            int rl0 = wm * 64 + mi * 16 + (lane >> 2);
            int rl1 = rl0 + 8;
            if (FUSED) {
                int col = n0 * 64 + wn * 32 + nt * 4 + (lane & 3);
                if (m0 + rl0 < M)
                    C[(size_t)s_cRow[rl0] * cStride + col] = silu_f(c[0]) * c[1];
                if (m0 + rl1 < M)
                    C[(size_t)s_cRow[rl1] * cStride + col] = silu_f(c[2]) * c[3];
            } else {
                int col = n0 * BROWS + wn * 64 + nt * 8 + 2 * (lane & 3);
                if (m0 + rl0 < M) {
                    float2 o; o.x = c[0]; o.y = c[1];
                    *(float2*)(C + (size_t)s_cRow[rl0] * cStride + col) = o;
                }
                if (m0 + rl1 < M) {
                    float2 o; o.x = c[2]; o.y = c[3];
                    *(float2*)(C + (size_t)s_cRow[rl1] * cStride + col) = o;
                }
            }
        }
    }
}

// ---------------- combine ----------------
__global__ void combine_kernel(float* __restrict__ out,
                               const float* __restrict__ so,
                               const float* __restrict__ part,
                               const float* __restrict__ tw)
{
    int idx = blockIdx.x * blockDim.x + threadIdx.x;
    if (idx >= T_TOK * HID / 4) return;
    int t = idx / (HID / 4);
    int c = (idx % (HID / 4)) * 4;
    float4 acc = *(const float4*)(so + (size_t)t * HID + c);
#pragma unroll
    for (int s = 0; s < TOPK; s++) {
        float w = tw[t * TOPK + s];
        float4 pv = *(const float4*)(part + (size_t)(t * TOPK + s) * HID + c);
        acc.x = fmaf(w, pv.x, acc.x);
        acc.y = fmaf(w, pv.y, acc.y);
        acc.z = fmaf(w, pv.z, acc.z);
        acc.w = fmaf(w, pv.w, acc.w);
    }
    *(float4*)(out + (size_t)t * HID + c) = acc;
}

// ---------------- launch ----------------
extern "C" void kernel_launch(void* const* d_in, const int* in_sizes, int n_in,
                              void* d_out, int out_size)
{
    (void)in_sizes; (void)n_in; (void)out_size;
    const float* X    = (const float*)d_in[0];
    const float* gw   = (const float*)d_in[1];
    const float* bias = (const float*)d_in[2];
    const float* w1   = (const float*)d_in[3];
    const float* w2   = (const float*)d_in[4];
    const float* sw1  = (const float*)d_in[5];
    const float* sw2  = (const float*)d_in[6];
    float* out = (float*)d_out;

    float *p_hb, *p_hs, *p_part, *p_so, *p_tw;
    int *p_cnt, *p_list;
    cudaGetSymbolAddress((void**)&p_hb,   g_hb);
    cudaGetSymbolAddress((void**)&p_hs,   g_hs);
    cudaGetSymbolAddress((void**)&p_part, g_part);
    cudaGetSymbolAddress((void**)&p_so,   g_so);
    cudaGetSymbolAddress((void**)&p_tw,   g_tw);
    cudaGetSymbolAddress((void**)&p_cnt,  g_cnt);
    cudaGetSymbolAddress((void**)&p_list, g_list);

    const size_t dynsm = NSTAGE * STAGE_B + 1024;
    cudaFuncSetAttribute(mma_gemm<true>,  cudaFuncAttributeMaxDynamicSharedMemorySize, (int)dynsm);
    cudaFuncSetAttribute(mma_gemm<false>, cudaFuncAttributeMaxDynamicSharedMemorySize, (int)dynsm);

    // 1. router
    zero_cnt_kernel<<<1, 32>>>(p_cnt);
    router_kernel<<<T_TOK, 256>>>(X, gw, bias, p_cnt, p_list, p_tw);

    // 2. shared expert
    mma_gemm<true><<<dim3(ISH / 64, T_TOK / BM, 1), NTHR, dynsm>>>(
        X, sw1, 0, p_hs, ISH, ISH, T_TOK, nullptr, HID, nullptr, 1);
    mma_gemm<false><<<dim3(HID / BROWS, T_TOK / BM, 1), NTHR, dynsm>>>(
        p_hs, sw2, 0, p_so, HID, 0, T_TOK, nullptr, ISH, nullptr, 1);

    // 3. routed experts
    mma_gemm<true><<<dim3(IMID / 64, 8, NEXP), NTHR, dynsm>>>(
        X, w1, (long long)(2 * IMID) * HID, p_hb, IMID, IMID,
        0, p_cnt, HID, p_list, TOPK);
    mma_gemm<false><<<dim3(HID / BROWS, 8, NEXP), NTHR, dynsm>>>(
        p_hb, w2, (long long)HID * IMID, p_part, HID, 0,
        0, p_cnt, IMID, p_list, 1);

    // 4. combine
    combine_kernel<<<(T_TOK * HID / 4 + 255) / 256, 256>>>(out, p_so, p_part, p_tw);
}

// round 11
// speedup vs baseline: 1.3220x; 1.3137x over previous
#include <cuda_runtime.h>
#include <cuda_fp16.h>
#include <cstdint>
#include <math.h>

#define T_TOK 1024
#define HID   2048
#define IMID  1024
#define NEXP  16
#define TOPK  6
#define NPAIR (T_TOK * TOPK)
#define ISH   2048
#define RSCALE 2.5f

// ---------------- scratch ----------------
__device__ float g_hb [(size_t)NPAIR * IMID];
__device__ float g_hs [(size_t)T_TOK * ISH];
__device__ float g_part[(size_t)NPAIR * HID];
__device__ float g_so [(size_t)T_TOK * HID];
__device__ int   g_cnt [NEXP];
__device__ int   g_list[NEXP * T_TOK];
__device__ float g_tw  [T_TOK * TOPK];

// ---------------- helpers ----------------
__device__ __forceinline__ uint32_t smem_u32(const void* p) {
    uint32_t a;
    asm("{ .reg .u64 t; cvta.to.shared.u64 t, %1; cvt.u32.u64 %0, t; }" : "=r"(a) : "l"(p));
    return a;
}
__device__ __forceinline__ float silu_f(float x) { return x / (1.f + expf(-x)); }

#define LDSM4(r, addr) \
    asm volatile("ldmatrix.sync.aligned.m8n8.x4.shared.b16 {%0,%1,%2,%3}, [%4];" \
        : "=r"((r)[0]), "=r"((r)[1]), "=r"((r)[2]), "=r"((r)[3]) : "r"(addr))

__device__ __forceinline__ void mma_f16(float* c, const uint32_t* a, const uint32_t* b) {
    asm volatile(
        "mma.sync.aligned.m16n8k16.row.col.f32.f16.f16.f32 "
        "{%0,%1,%2,%3}, {%4,%5,%6,%7}, {%8,%9}, {%0,%1,%2,%3};"
        : "+f"(c[0]), "+f"(c[1]), "+f"(c[2]), "+f"(c[3])
        : "r"(a[0]), "r"(a[1]), "r"(a[2]), "r"(a[3]), "r"(b[0]), "r"(b[1]));
}

// 384 threads: 8 consumer warps + 4 producer warps
#define NTHR 384
#define NCONS 256
#define NSTAGE 3
#define BAR_SYNC(id)   asm volatile("bar.sync %0, %1;"   :: "r"(id), "r"(NTHR) : "memory")
#define BAR_ARRIVE(id) asm volatile("bar.arrive %0, %1;" :: "r"(id), "r"(NTHR) : "memory")
// ids: 1..3 = full[stage], 4..6 = empty[stage]

// ---------------- router ----------------
__global__ void zero_cnt_kernel(int* cnt) { if (threadIdx.x < NEXP) cnt[threadIdx.x] = 0; }

__global__ void __launch_bounds__(256)
router_kernel(const float* __restrict__ X, const float* __restrict__ gw,
              const float* __restrict__ bias,
              int* __restrict__ cnt, int* __restrict__ list, float* __restrict__ tw)
{
    int t = blockIdx.x;
    __shared__ float red[NEXP * 256];
    float acc[NEXP];
#pragma unroll
    for (int e = 0; e < NEXP; e++) acc[e] = 0.f;
    const float* x = X + (size_t)t * HID;
    for (int h = threadIdx.x; h < HID; h += 256) {
        float xv = x[h];
#pragma unroll
        for (int e = 0; e < NEXP; e++) acc[e] += xv * gw[e * HID + h];
    }
#pragma unroll
    for (int e = 0; e < NEXP; e++) red[e * 256 + threadIdx.x] = acc[e];
    __syncthreads();
    for (int s = 128; s > 0; s >>= 1) {
        if (threadIdx.x < s) {
#pragma unroll
            for (int e = 0; e < NEXP; e++)
                red[e * 256 + threadIdx.x] += red[e * 256 + threadIdx.x + s];
        }
        __syncthreads();
    }
    if (threadIdx.x == 0) {
        float sc[NEXP], ch[NEXP];
#pragma unroll
        for (int e = 0; e < NEXP; e++) {
            float l = red[e * 256];
            float s = 1.f / (1.f + expf(-l));
            sc[e] = s; ch[e] = s + bias[e];
        }
        bool used[NEXP];
#pragma unroll
        for (int e = 0; e < NEXP; e++) used[e] = false;
        int sel[TOPK]; float wsum = 0.f;
        for (int k = 0; k < TOPK; k++) {
            float best = -1e30f; int bi = 0;
            for (int e = 0; e < NEXP; e++)
                if (!used[e] && ch[e] > best) { best = ch[e]; bi = e; }
            used[bi] = true; sel[k] = bi; wsum += sc[bi];
        }
        float inv = RSCALE / wsum;
        for (int k = 0; k < TOPK; k++) {
            tw[t * TOPK + k] = sc[sel[k]] * inv;
            int pos = atomicAdd(&cnt[sel[k]], 1);
            list[sel[k] * T_TOK + pos] = t * TOPK + k;
        }
    }
}

// ---------------- warp-specialized 2-pass fp16 MMA GEMM ----------------
// C = (hiA + loA) * hiB  ==  A (fp32-exact) x fp16-rounded B.
// SMEM per stage: Ahi [128x64], Alo [128x64], Bhi [128x64] fp16 tiles = 48 KB.
// 8 consumer warps (4M x 2N, 32x64) + 4 producer warps, 3-stage pipe.
#define BM 128
#define BROWS 128
#define TILE_B 16384
#define STAGE_B 49152

template<bool FUSED>
__global__ void __launch_bounds__(NTHR, 1)
mma_gemm(const float* __restrict__ A,
         const float* __restrict__ Bbase, long long bStride,
         float* __restrict__ C, int cStride, int upOff,
         int Mfixed, const int* __restrict__ cnt, int K,
         const int* __restrict__ list, int adiv)
{
    const int e = blockIdx.z;
    const int M = cnt ? cnt[e] : Mfixed;
    const int m0 = blockIdx.y * BM;
    if (m0 >= M) return;
    const int n0 = blockIdx.x;
    const float* B = Bbase + (size_t)e * bStride;
    const int* lst = list ? (list + e * T_TOK) : nullptr;

    extern __shared__ char dynraw[];
    char* dyn = (char*)(((uintptr_t)dynraw + 1023) & ~(uintptr_t)1023);
    const uint32_t dynu = smem_u32(dyn);

    __shared__ int s_aOff[BM];
    __shared__ int s_cRow[BM];
    __shared__ int s_bRow[BROWS];

    const int tid = threadIdx.x;
    const int lane = tid & 31;
    const int warp = tid >> 5;

    if (tid < BM) {
        int r = m0 + tid; if (r > M - 1) r = M - 1;
        int pr = lst ? lst[r] : r;
        s_cRow[tid] = pr;
        s_aOff[tid] = (lst ? pr / adiv : pr) * K;
        int bj;
        if (FUSED) bj = (tid >> 1) + n0 * 64 + ((tid & 1) ? upOff : 0);
        else       bj = n0 * BROWS + tid;
        s_bRow[tid] = bj;
    }
    __syncthreads();

    const int NC = K >> 6;

    if (warp >= 8) {
        // ================= PRODUCER (warps 8..11, 128 threads) =================
        const int ptid = tid - NCONS;
        const int pr8 = ptid >> 4;          // base row 0..7
        const int pc4 = ptid & 15;          // float4 column

        for (int i = 0; i < NC; i++) {
            const int s = i % NSTAGE;
            if (i >= NSTAGE) BAR_SYNC(4 + s);       // wait empty
            char* sb = dyn + s * STAGE_B;
            const int k0 = i << 6;

            float4 va[8], vb[8];

#define LOADG(gidx, vv)                                                          \
            _Pragma("unroll")                                                    \
            for (int j = 0; j < 8; j++) {                                        \
                const int slot = (gidx) * 8 + j;                                 \
                const int row = pr8 + 8 * (slot & 15);                           \
                const int off = (slot < 16) ? s_aOff[row]                        \
                                            : (s_bRow[row] * K);                 \
                (vv)[j] = *(const float4*)(((slot < 16) ? A : B) + off +         \
                                           pc4 * 4 + k0);                        \
            }
// A slots (slot<16): store hi at [0,16K) and lo at [16K,32K).
// B slots: store hi only at [32K,48K).
#define STOREG(gidx, vv)                                                         \
            _Pragma("unroll")                                                    \
            for (int j = 0; j < 8; j++) {                                        \
                const int slot = (gidx) * 8 + j;                                 \
                const int row = pr8 + 8 * (slot & 15);                           \
                uint32_t swz = (uint32_t)(row * 128 + pc4 * 8);                  \
                swz ^= (uint32_t)(row & 7) << 4;                                 \
                float4 x = (vv)[j];                                              \
                __half2 h01 = __floats2half2_rn(x.x, x.y);                       \
                __half2 h23 = __floats2half2_rn(x.z, x.w);                       \
                uint2 hw;                                                        \
                hw.x = *(uint32_t*)&h01; hw.y = *(uint32_t*)&h23;                \
                if (slot < 16) {                                                 \
                    float r0 = x.x - __low2float(h01);                           \
                    float r1 = x.y - __high2float(h01);                          \
                    float r2 = x.z - __low2float(h23);                           \
                    float r3 = x.w - __high2float(h23);                          \
                    __half2 l01 = __floats2half2_rn(r0, r1);                     \
                    __half2 l23 = __floats2half2_rn(r2, r3);                     \
                    uint2 lw;                                                    \
                    lw.x = *(uint32_t*)&l01; lw.y = *(uint32_t*)&l23;            \
                    *(uint2*)(sb + swz) = hw;                                    \
                    *(uint2*)(sb + swz + TILE_B) = lw;                           \
                } else {                                                         \
                    *(uint2*)(sb + 2u * TILE_B + swz) = hw;                      \
                }                                                                \
            }

            LOADG(0, va)
            LOADG(1, vb) STOREG(0, va)
            LOADG(2, va) STOREG(1, vb)
            LOADG(3, vb) STOREG(2, va)
            STOREG(3, vb)
#undef LOADG
#undef STOREG
            BAR_ARRIVE(1 + s);                      // signal full
        }
        return;
    }

    // ================= CONSUMER (warps 0..7; 4M x 2N, 32x64 tile) =================
    const int wm = warp & 3;
    const int wn = warp >> 2;
    const int aRow0 = wm * 32 + (lane & 7) + ((lane >> 3) & 1) * 8;
    const uint32_t aHi16 = ((lane >> 4) & 1) * 16;
    const uint32_t xorA = (uint32_t)(aRow0 & 7) << 4;
    const int bRow0 = wn * 64 + (lane & 7) + ((lane >> 4) & 1) * 8;
    const uint32_t bHi16 = ((lane >> 3) & 1) * 16;
    const uint32_t xorB = (uint32_t)(bRow0 & 7) << 4;

    float acc[2][8][4];
#pragma unroll
    for (int a = 0; a < 2; a++)
#pragma unroll
        for (int b = 0; b < 8; b++)
#pragma unroll
            for (int c = 0; c < 4; c++) acc[a][b][c] = 0.f;

    for (int i = 0; i < NC; i++) {
        const int s = i % NSTAGE;
        BAR_SYNC(1 + s);                            // wait full
        const uint32_t su = dynu + s * STAGE_B;
#pragma unroll
        for (int ks = 0; ks < 4; ks++) {
            uint32_t aH[8], aL[8];
#pragma unroll
            for (int g = 0; g < 2; g++) {
                uint32_t ao = su + (uint32_t)(aRow0 + g * 16) * 128 +
                              (((uint32_t)ks * 32 + aHi16) ^ xorA);
                LDSM4(&aH[g * 4], ao);
                LDSM4(&aL[g * 4], ao + TILE_B);
            }
#pragma unroll
            for (int nh = 0; nh < 2; nh++) {
                uint32_t bH[8];
#pragma unroll
                for (int q = 0; q < 2; q++) {
                    uint32_t bo = su + 2 * TILE_B +
                                  (uint32_t)(bRow0 + nh * 32 + q * 16) * 128 +
                                  (((uint32_t)ks * 32 + bHi16) ^ xorB);
                    LDSM4(&bH[q * 4], bo);
                }
                // pass 1: hiA x hiB (8 independent)
#pragma unroll
                for (int mi = 0; mi < 2; mi++)
#pragma unroll
                    for (int ni = 0; ni < 4; ni++)
                        mma_f16(acc[mi][nh * 4 + ni], &aH[mi * 4],
                                &bH[(ni >> 1) * 4 + (ni & 1) * 2]);
                // pass 2: loA x hiB (8 independent)
#pragma unroll
                for (int mi = 0; mi < 2; mi++)
#pragma unroll
                    for (int ni = 0; ni < 4; ni++)
                        mma_f16(acc[mi][nh * 4 + ni], &aL[mi * 4],
                                &bH[(ni >> 1) * 4 + (ni & 1) * 2]);
            }
        }
        if (i + NSTAGE < NC) BAR_ARRIVE(4 + s);     // signal empty
    }

    // ---- epilogue ----
#pragma unroll
    for (int mi = 0; mi < 2; mi++) {
#pragma unroll
        for (int nt = 0; nt < 8; nt++) {
            const float* c = acc[mi][nt];
            int rl0 = wm * 32 + mi * 16 + (lane >> 2);
            int rl1 = rl0 + 8;
            if (FUSED) {
                int col = n0 * 64 + wn * 32 + nt * 4 + (lane & 3);
                if (m0 + rl0 < M)
                    C[(size_t)s_cRow[rl0] * cStride + col] = silu_f(c[0]) * c[1];
                if (m0 + rl1 < M)
                    C[(size_t)s_cRow[rl1] * cStride + col] = silu_f(c[2]) * c[3];
            } else {
                int col = n0 * BROWS + wn * 64 + nt * 8 + 2 * (lane & 3);
                if (m0 + rl0 < M) {
                    float2 o; o.x = c[0]; o.y = c[1];
                    *(float2*)(C + (size_t)s_cRow[rl0] * cStride + col) = o;
                }
                if (m0 + rl1 < M) {
                    float2 o; o.x = c[2]; o.y = c[3];
                    *(float2*)(C + (size_t)s_cRow[rl1] * cStride + col) = o;
                }
            }
        }
    }
}

// ---------------- combine ----------------
__global__ void combine_kernel(float* __restrict__ out,
                               const float* __restrict__ so,
                               const float* __restrict__ part,
                               const float* __restrict__ tw)
{
    int idx = blockIdx.x * blockDim.x + threadIdx.x;
    if (idx >= T_TOK * HID / 4) return;
    int t = idx / (HID / 4);
    int c = (idx % (HID / 4)) * 4;
    float4 acc = *(const float4*)(so + (size_t)t * HID + c);
#pragma unroll
    for (int s = 0; s < TOPK; s++) {
        float w = tw[t * TOPK + s];
        float4 pv = *(const float4*)(part + (size_t)(t * TOPK + s) * HID + c);
        acc.x = fmaf(w, pv.x, acc.x);
        acc.y = fmaf(w, pv.y, acc.y);
        acc.z = fmaf(w, pv.z, acc.z);
        acc.w = fmaf(w, pv.w, acc.w);
    }
    *(float4*)(out + (size_t)t * HID + c) = acc;
}

// ---------------- launch ----------------
extern "C" void kernel_launch(void* const* d_in, const int* in_sizes, int n_in,
                              void* d_out, int out_size)
{
    (void)in_sizes; (void)n_in; (void)out_size;
    const float* X    = (const float*)d_in[0];
    const float* gw   = (const float*)d_in[1];
    const float* bias = (const float*)d_in[2];
    const float* w1   = (const float*)d_in[3];
    const float* w2   = (const float*)d_in[4];
    const float* sw1  = (const float*)d_in[5];
    const float* sw2  = (const float*)d_in[6];
    float* out = (float*)d_out;

    float *p_hb, *p_hs, *p_part, *p_so, *p_tw;
    int *p_cnt, *p_list;
    cudaGetSymbolAddress((void**)&p_hb,   g_hb);
    cudaGetSymbolAddress((void**)&p_hs,   g_hs);
    cudaGetSymbolAddress((void**)&p_part, g_part);
    cudaGetSymbolAddress((void**)&p_so,   g_so);
    cudaGetSymbolAddress((void**)&p_tw,   g_tw);
    cudaGetSymbolAddress((void**)&p_cnt,  g_cnt);
    cudaGetSymbolAddress((void**)&p_list, g_list);

    const size_t dynsm = NSTAGE * STAGE_B + 1024;
    cudaFuncSetAttribute(mma_gemm<true>,  cudaFuncAttributeMaxDynamicSharedMemorySize, (int)dynsm);
    cudaFuncSetAttribute(mma_gemm<false>, cudaFuncAttributeMaxDynamicSharedMemorySize, (int)dynsm);

    // 1. router
    zero_cnt_kernel<<<1, 32>>>(p_cnt);
    router_kernel<<<T_TOK, 256>>>(X, gw, bias, p_cnt, p_list, p_tw);

    // 2. shared expert
    mma_gemm<true><<<dim3(ISH / 64, T_TOK / BM, 1), NTHR, dynsm>>>(
        X, sw1, 0, p_hs, ISH, ISH, T_TOK, nullptr, HID, nullptr, 1);
    mma_gemm<false><<<dim3(HID / BROWS, T_TOK / BM, 1), NTHR, dynsm>>>(
        p_hs, sw2, 0, p_so, HID, 0, T_TOK, nullptr, ISH, nullptr, 1);

    // 3. routed experts
    mma_gemm<true><<<dim3(IMID / 64, 8, NEXP), NTHR, dynsm>>>(
        X, w1, (long long)(2 * IMID) * HID, p_hb, IMID, IMID,
        0, p_cnt, HID, p_list, TOPK);
    mma_gemm<false><<<dim3(HID / BROWS, 8, NEXP), NTHR, dynsm>>>(
        p_hb, w2, (long long)HID * IMID, p_part, HID, 0,
        0, p_cnt, IMID, p_list, 1);

    // 4. combine
    combine_kernel<<<(T_TOK * HID / 4 + 255) / 256, 256>>>(out, p_so, p_part, p_tw);
}

// round 12
// speedup vs baseline: 1.4250x; 1.0779x over previous
#include <cuda_runtime.h>
#include <cuda_fp16.h>
#include <cstdint>
#include <math.h>

#define T_TOK 1024
#define HID   2048
#define IMID  1024
#define NEXP  16
#define TOPK  6
#define NPAIR (T_TOK * TOPK)
#define ISH   2048
#define RSCALE 2.5f

// ---------------- scratch ----------------
__device__ float g_hb [(size_t)NPAIR * IMID];
__device__ float g_hs [(size_t)T_TOK * ISH];
__device__ float g_part[(size_t)NPAIR * HID];
__device__ float g_so [(size_t)T_TOK * HID];
__device__ int   g_cnt [NEXP];
__device__ int   g_list[NEXP * T_TOK];
__device__ float g_tw  [T_TOK * TOPK];

// ---------------- helpers ----------------
__device__ __forceinline__ uint32_t smem_u32(const void* p) {
    uint32_t a;
    asm("{ .reg .u64 t; cvta.to.shared.u64 t, %1; cvt.u32.u64 %0, t; }" : "=r"(a) : "l"(p));
    return a;
}
__device__ __forceinline__ float silu_f(float x) { return x / (1.f + expf(-x)); }

#define LDSM4(r, addr) \
    asm volatile("ldmatrix.sync.aligned.m8n8.x4.shared.b16 {%0,%1,%2,%3}, [%4];" \
        : "=r"((r)[0]), "=r"((r)[1]), "=r"((r)[2]), "=r"((r)[3]) : "r"(addr))

__device__ __forceinline__ void mma_f16(float* c, const uint32_t* a, const uint32_t* b) {
    asm volatile(
        "mma.sync.aligned.m16n8k16.row.col.f32.f16.f16.f32 "
        "{%0,%1,%2,%3}, {%4,%5,%6,%7}, {%8,%9}, {%0,%1,%2,%3};"
        : "+f"(c[0]), "+f"(c[1]), "+f"(c[2]), "+f"(c[3])
        : "r"(a[0]), "r"(a[1]), "r"(a[2]), "r"(a[3]), "r"(b[0]), "r"(b[1]));
}

// 384 threads: 8 consumer warps + 4 producer warps
#define NTHR 384
#define NCONS 256
#define NSTAGE 4
#define BAR_SYNC(id)   asm volatile("bar.sync %0, %1;"   :: "r"(id), "r"(NTHR) : "memory")
#define BAR_ARRIVE(id) asm volatile("bar.arrive %0, %1;" :: "r"(id), "r"(NTHR) : "memory")
// ids: 1..4 = full[stage], 5..8 = empty[stage]

// ---------------- router ----------------
__global__ void zero_cnt_kernel(int* cnt) { if (threadIdx.x < NEXP) cnt[threadIdx.x] = 0; }

__global__ void __launch_bounds__(256)
router_kernel(const float* __restrict__ X, const float* __restrict__ gw,
              const float* __restrict__ bias,
              int* __restrict__ cnt, int* __restrict__ list, float* __restrict__ tw)
{
    int t = blockIdx.x;
    __shared__ float red[NEXP * 256];
    float acc[NEXP];
#pragma unroll
    for (int e = 0; e < NEXP; e++) acc[e] = 0.f;
    const float* x = X + (size_t)t * HID;
    for (int h = threadIdx.x; h < HID; h += 256) {
        float xv = x[h];
#pragma unroll
        for (int e = 0; e < NEXP; e++) acc[e] += xv * gw[e * HID + h];
    }
#pragma unroll
    for (int e = 0; e < NEXP; e++) red[e * 256 + threadIdx.x] = acc[e];
    __syncthreads();
    for (int s = 128; s > 0; s >>= 1) {
        if (threadIdx.x < s) {
#pragma unroll
            for (int e = 0; e < NEXP; e++)
                red[e * 256 + threadIdx.x] += red[e * 256 + threadIdx.x + s];
        }
        __syncthreads();
    }
    if (threadIdx.x == 0) {
        float sc[NEXP], ch[NEXP];
#pragma unroll
        for (int e = 0; e < NEXP; e++) {
            float l = red[e * 256];
            float s = 1.f / (1.f + expf(-l));
            sc[e] = s; ch[e] = s + bias[e];
        }
        bool used[NEXP];
#pragma unroll
        for (int e = 0; e < NEXP; e++) used[e] = false;
        int sel[TOPK]; float wsum = 0.f;
        for (int k = 0; k < TOPK; k++) {
            float best = -1e30f; int bi = 0;
            for (int e = 0; e < NEXP; e++)
                if (!used[e] && ch[e] > best) { best = ch[e]; bi = e; }
            used[bi] = true; sel[k] = bi; wsum += sc[bi];
        }
        float inv = RSCALE / wsum;
        for (int k = 0; k < TOPK; k++) {
            tw[t * TOPK + k] = sc[sel[k]] * inv;
            int pos = atomicAdd(&cnt[sel[k]], 1);
            list[sel[k] * T_TOK + pos] = t * TOPK + k;
        }
    }
}

// ---------------- warp-specialized single-pass fp16 MMA GEMM ----------------
// C = fp16(A) x fp16(B), fp32 accumulate.
// SMEM per stage: Ahi [128x64] + Bhi [128x64] fp16 = 32 KB. 4-stage pipe.
// 8 consumer warps (4M x 2N, 32x64) + 4 producer warps.
#define BM 128
#define BROWS 128
#define TILE_B 16384
#define STAGE_B 32768

template<bool FUSED>
__global__ void __launch_bounds__(NTHR, 1)
mma_gemm(const float* __restrict__ A,
         const float* __restrict__ Bbase, long long bStride,
         float* __restrict__ C, int cStride, int upOff,
         int Mfixed, const int* __restrict__ cnt, int K,
         const int* __restrict__ list, int adiv)
{
    const int e = blockIdx.z;
    const int M = cnt ? cnt[e] : Mfixed;
    const int m0 = blockIdx.y * BM;
    if (m0 >= M) return;
    const int n0 = blockIdx.x;
    const float* B = Bbase + (size_t)e * bStride;
    const int* lst = list ? (list + e * T_TOK) : nullptr;

    extern __shared__ char dynraw[];
    char* dyn = (char*)(((uintptr_t)dynraw + 1023) & ~(uintptr_t)1023);
    const uint32_t dynu = smem_u32(dyn);

    __shared__ int s_aOff[BM];
    __shared__ int s_cRow[BM];
    __shared__ int s_bRow[BROWS];

    const int tid = threadIdx.x;
    const int lane = tid & 31;
    const int warp = tid >> 5;

    if (tid < BM) {
        int r = m0 + tid; if (r > M - 1) r = M - 1;
        int pr = lst ? lst[r] : r;
        s_cRow[tid] = pr;
        s_aOff[tid] = (lst ? pr / adiv : pr) * K;
        int bj;
        if (FUSED) bj = (tid >> 1) + n0 * 64 + ((tid & 1) ? upOff : 0);
        else       bj = n0 * BROWS + tid;
        s_bRow[tid] = bj;
    }
    __syncthreads();

    const int NC = K >> 6;

    if (warp >= 8) {
        // ================= PRODUCER (warps 8..11, 128 threads) =================
        const int ptid = tid - NCONS;
        const int pr8 = ptid >> 4;          // base row 0..7
        const int pc4 = ptid & 15;          // float4 column

        for (int i = 0; i < NC; i++) {
            const int s = i % NSTAGE;
            if (i >= NSTAGE) BAR_SYNC(5 + s);       // wait empty
            char* sb = dyn + s * STAGE_B;
            const int k0 = i << 6;

            float4 va[8], vb[8];

#define LOADG(gidx, vv)                                                          \
            _Pragma("unroll")                                                    \
            for (int j = 0; j < 8; j++) {                                        \
                const int slot = (gidx) * 8 + j;                                 \
                const int row = pr8 + 8 * (slot & 15);                           \
                const int off = (slot < 16) ? s_aOff[row]                        \
                                            : (s_bRow[row] * K);                 \
                (vv)[j] = *(const float4*)(((slot < 16) ? A : B) + off +         \
                                           pc4 * 4 + k0);                        \
            }
// A slots (slot<16): hi at [0,16K). B slots: hi at [16K,32K).
#define STOREG(gidx, vv)                                                         \
            _Pragma("unroll")                                                    \
            for (int j = 0; j < 8; j++) {                                        \
                const int slot = (gidx) * 8 + j;                                 \
                const int row = pr8 + 8 * (slot & 15);                           \
                uint32_t swz = (uint32_t)(row * 128 + pc4 * 8);                  \
                swz ^= (uint32_t)(row & 7) << 4;                                 \
                float4 x = (vv)[j];                                              \
                __half2 h01 = __floats2half2_rn(x.x, x.y);                       \
                __half2 h23 = __floats2half2_rn(x.z, x.w);                       \
                uint2 hw;                                                        \
                hw.x = *(uint32_t*)&h01; hw.y = *(uint32_t*)&h23;                \
                uint32_t o = ((slot < 16) ? 0u : (uint32_t)TILE_B) + swz;        \
                *(uint2*)(sb + o) = hw;                                          \
            }

            LOADG(0, va)
            LOADG(1, vb) STOREG(0, va)
            LOADG(2, va) STOREG(1, vb)
            LOADG(3, vb) STOREG(2, va)
            STOREG(3, vb)
#undef LOADG
#undef STOREG
            BAR_ARRIVE(1 + s);                      // signal full
        }
        return;
    }

    // ================= CONSUMER (warps 0..7; 4M x 2N, 32x64 tile) =================
    const int wm = warp & 3;
    const int wn = warp >> 2;
    const int aRow0 = wm * 32 + (lane & 7) + ((lane >> 3) & 1) * 8;
    const uint32_t aHi16 = ((lane >> 4) & 1) * 16;
    const uint32_t xorA = (uint32_t)(aRow0 & 7) << 4;
    const int bRow0 = wn * 64 + (lane & 7) + ((lane >> 4) & 1) * 8;
    const uint32_t bHi16 = ((lane >> 3) & 1) * 16;
    const uint32_t xorB = (uint32_t)(bRow0 & 7) << 4;

    float acc[2][8][4];
#pragma unroll
    for (int a = 0; a < 2; a++)
#pragma unroll
        for (int b = 0; b < 8; b++)
#pragma unroll
            for (int c = 0; c < 4; c++) acc[a][b][c] = 0.f;

    for (int i = 0; i < NC; i++) {
        const int s = i % NSTAGE;
        BAR_SYNC(1 + s);                            // wait full
        const uint32_t su = dynu + s * STAGE_B;
#pragma unroll
        for (int ks = 0; ks < 4; ks++) {
            uint32_t aH[8];
#pragma unroll
            for (int g = 0; g < 2; g++) {
                uint32_t ao = su + (uint32_t)(aRow0 + g * 16) * 128 +
                              (((uint32_t)ks * 32 + aHi16) ^ xorA);
                LDSM4(&aH[g * 4], ao);
            }
#pragma unroll
            for (int nh = 0; nh < 2; nh++) {
                uint32_t bH[8];
#pragma unroll
                for (int q = 0; q < 2; q++) {
                    uint32_t bo = su + TILE_B +
                                  (uint32_t)(bRow0 + nh * 32 + q * 16) * 128 +
                                  (((uint32_t)ks * 32 + bHi16) ^ xorB);
                    LDSM4(&bH[q * 4], bo);
                }
#pragma unroll
                for (int mi = 0; mi < 2; mi++)
#pragma unroll
                    for (int ni = 0; ni < 4; ni++)
                        mma_f16(acc[mi][nh * 4 + ni], &aH[mi * 4],
                                &bH[(ni >> 1) * 4 + (ni & 1) * 2]);
            }
        }
        if (i + NSTAGE < NC) BAR_ARRIVE(5 + s);     // signal empty
    }

    // ---- epilogue ----
#pragma unroll
    for (int mi = 0; mi < 2; mi++) {
#pragma unroll
        for (int nt = 0; nt < 8; nt++) {
            const float* c = acc[mi][nt];
            int rl0 = wm * 32 + mi * 16 + (lane >> 2);
            int rl1 = rl0 + 8;
            if (FUSED) {
                int col = n0 * 64 + wn * 32 + nt * 4 + (lane & 3);
                if (m0 + rl0 < M)
                    C[(size_t)s_cRow[rl0] * cStride + col] = silu_f(c[0]) * c[1];
                if (m0 + rl1 < M)
                    C[(size_t)s_cRow[rl1] * cStride + col] = silu_f(c[2]) * c[3];
            } else {
                int col = n0 * BROWS + wn * 64 + nt * 8 + 2 * (lane & 3);
                if (m0 + rl0 < M) {
                    float2 o; o.x = c[0]; o.y = c[1];
                    *(float2*)(C + (size_t)s_cRow[rl0] * cStride + col) = o;
                }
                if (m0 + rl1 < M) {
                    float2 o; o.x = c[2]; o.y = c[3];
                    *(float2*)(C + (size_t)s_cRow[rl1] * cStride + col) = o;
                }
            }
        }
    }
}

// ---------------- combine ----------------
__global__ void combine_kernel(float* __restrict__ out,
                               const float* __restrict__ so,
                               const float* __restrict__ part,
                               const float* __restrict__ tw)
{
    int idx = blockIdx.x * blockDim.x + threadIdx.x;
    if (idx >= T_TOK * HID / 4) return;
    int t = idx / (HID / 4);
    int c = (idx % (HID / 4)) * 4;
    float4 acc = *(const float4*)(so + (size_t)t * HID + c);
#pragma unroll
    for (int s = 0; s < TOPK; s++) {
        float w = tw[t * TOPK + s];
        float4 pv = *(const float4*)(part + (size_t)(t * TOPK + s) * HID + c);
        acc.x = fmaf(w, pv.x, acc.x);
        acc.y = fmaf(w, pv.y, acc.y);
        acc.z = fmaf(w, pv.z, acc.z);
        acc.w = fmaf(w, pv.w, acc.w);
    }
    *(float4*)(out + (size_t)t * HID + c) = acc;
}

// ---------------- launch ----------------
extern "C" void kernel_launch(void* const* d_in, const int* in_sizes, int n_in,
                              void* d_out, int out_size)
{
    (void)in_sizes; (void)n_in; (void)out_size;
    const float* X    = (const float*)d_in[0];
    const float* gw   = (const float*)d_in[1];
    const float* bias = (const float*)d_in[2];
    const float* w1   = (const float*)d_in[3];
    const float* w2   = (const float*)d_in[4];
    const float* sw1  = (const float*)d_in[5];
    const float* sw2  = (const float*)d_in[6];
    float* out = (float*)d_out;

    float *p_hb, *p_hs, *p_part, *p_so, *p_tw;
    int *p_cnt, *p_list;
    cudaGetSymbolAddress((void**)&p_hb,   g_hb);
    cudaGetSymbolAddress((void**)&p_hs,   g_hs);
    cudaGetSymbolAddress((void**)&p_part, g_part);
    cudaGetSymbolAddress((void**)&p_so,   g_so);
    cudaGetSymbolAddress((void**)&p_tw,   g_tw);
    cudaGetSymbolAddress((void**)&p_cnt,  g_cnt);
    cudaGetSymbolAddress((void**)&p_list, g_list);

    const size_t dynsm = NSTAGE * STAGE_B + 1024;
    cudaFuncSetAttribute(mma_gemm<true>,  cudaFuncAttributeMaxDynamicSharedMemorySize, (int)dynsm);
    cudaFuncSetAttribute(mma_gemm<false>, cudaFuncAttributeMaxDynamicSharedMemorySize, (int)dynsm);

    // 1. router
    zero_cnt_kernel<<<1, 32>>>(p_cnt);
    router_kernel<<<T_TOK, 256>>>(X, gw, bias, p_cnt, p_list, p_tw);

    // 2. shared expert
    mma_gemm<true><<<dim3(ISH / 64, T_TOK / BM, 1), NTHR, dynsm>>>(
        X, sw1, 0, p_hs, ISH, ISH, T_TOK, nullptr, HID, nullptr, 1);
    mma_gemm<false><<<dim3(HID / BROWS, T_TOK / BM, 1), NTHR, dynsm>>>(
        p_hs, sw2, 0, p_so, HID, 0, T_TOK, nullptr, ISH, nullptr, 1);

    // 3. routed experts
    mma_gemm<true><<<dim3(IMID / 64, 8, NEXP), NTHR, dynsm>>>(
        X, w1, (long long)(2 * IMID) * HID, p_hb, IMID, IMID,
        0, p_cnt, HID, p_list, TOPK);
    mma_gemm<false><<<dim3(HID / BROWS, 8, NEXP), NTHR, dynsm>>>(
        p_hb, w2, (long long)HID * IMID, p_part, HID, 0,
        0, p_cnt, IMID, p_list, 1);

    // 4. combine
    combine_kernel<<<(T_TOK * HID / 4 + 255) / 256, 256>>>(out, p_so, p_part, p_tw);
}

// round 13
// speedup vs baseline: 2.0210x; 1.4183x over previous
#include <cuda_runtime.h>
#include <cuda_fp16.h>
#include <cstdint>
#include <math.h>

#define T_TOK 1024
#define HID   2048
#define IMID  1024
#define NEXP  16
#define TOPK  6
#define NPAIR (T_TOK * TOPK)
#define ISH   2048
#define RSCALE 2.5f

// ---------------- scratch ----------------
__device__ __half g_w1h [(size_t)NEXP * 2 * IMID * HID];
__device__ __half g_w2h [(size_t)NEXP * HID * IMID];
__device__ __half g_sw1h[(size_t)2 * ISH * HID];
__device__ __half g_sw2h[(size_t)HID * ISH];
__device__ __half g_xh  [(size_t)T_TOK * HID];
__device__ __half g_hbh [(size_t)NPAIR * IMID];
__device__ __half g_hsh [(size_t)T_TOK * ISH];
__device__ float  g_part[(size_t)NPAIR * HID];
__device__ float  g_so  [(size_t)T_TOK * HID];
__device__ int    g_cnt [NEXP];
__device__ int    g_list[NEXP * T_TOK];
__device__ float  g_tw  [T_TOK * TOPK];

// ---------------- helpers ----------------
__device__ __forceinline__ uint32_t smem_u32(const void* p) {
    uint32_t a;
    asm("{ .reg .u64 t; cvta.to.shared.u64 t, %1; cvt.u32.u64 %0, t; }" : "=r"(a) : "l"(p));
    return a;
}
__device__ __forceinline__ float silu_f(float x) { return x / (1.f + expf(-x)); }

#define LDSM4(r, addr) \
    asm volatile("ldmatrix.sync.aligned.m8n8.x4.shared.b16 {%0,%1,%2,%3}, [%4];" \
        : "=r"((r)[0]), "=r"((r)[1]), "=r"((r)[2]), "=r"((r)[3]) : "r"(addr))

__device__ __forceinline__ void mma_f16(float* c, const uint32_t* a, const uint32_t* b) {
    asm volatile(
        "mma.sync.aligned.m16n8k16.row.col.f32.f16.f16.f32 "
        "{%0,%1,%2,%3}, {%4,%5,%6,%7}, {%8,%9}, {%0,%1,%2,%3};"
        : "+f"(c[0]), "+f"(c[1]), "+f"(c[2]), "+f"(c[3])
        : "r"(a[0]), "r"(a[1]), "r"(a[2]), "r"(a[3]), "r"(b[0]), "r"(b[1]));
}

#define CP_ASYNC16(dst, src) \
    asm volatile("cp.async.cg.shared.global [%0], [%1], 16;" :: "r"(dst), "l"(src))
#define CP_COMMIT() asm volatile("cp.async.commit_group;" ::: "memory")
#define CP_WAIT(n)  asm volatile("cp.async.wait_group %0;" :: "n"(n) : "memory")

// ---------------- fp32 -> fp16 conversion ----------------
__global__ void __launch_bounds__(256)
cvt_f2h(const float4* __restrict__ src, uint2* __restrict__ dst, int n4)
{
    int i = blockIdx.x * 256 + threadIdx.x;
    if (i >= n4) return;
    float4 v = src[i];
    __half2 a = __floats2half2_rn(v.x, v.y);
    __half2 b = __floats2half2_rn(v.z, v.w);
    dst[i] = make_uint2(*(uint32_t*)&a, *(uint32_t*)&b);
}

// ---------------- router ----------------
__global__ void zero_cnt_kernel(int* cnt) { if (threadIdx.x < NEXP) cnt[threadIdx.x] = 0; }

__global__ void __launch_bounds__(256)
router_kernel(const float* __restrict__ X, const float* __restrict__ gw,
              const float* __restrict__ bias,
              int* __restrict__ cnt, int* __restrict__ list, float* __restrict__ tw)
{
    int t = blockIdx.x;
    __shared__ float red[NEXP * 256];
    float acc[NEXP];
#pragma unroll
    for (int e = 0; e < NEXP; e++) acc[e] = 0.f;
    const float* x = X + (size_t)t * HID;
    for (int h = threadIdx.x; h < HID; h += 256) {
        float xv = x[h];
#pragma unroll
        for (int e = 0; e < NEXP; e++) acc[e] += xv * gw[e * HID + h];
    }
#pragma unroll
    for (int e = 0; e < NEXP; e++) red[e * 256 + threadIdx.x] = acc[e];
    __syncthreads();
    for (int s = 128; s > 0; s >>= 1) {
        if (threadIdx.x < s) {
#pragma unroll
            for (int e = 0; e < NEXP; e++)
                red[e * 256 + threadIdx.x] += red[e * 256 + threadIdx.x + s];
        }
        __syncthreads();
    }
    if (threadIdx.x == 0) {
        float sc[NEXP], ch[NEXP];
#pragma unroll
        for (int e = 0; e < NEXP; e++) {
            float l = red[e * 256];
            float s = 1.f / (1.f + expf(-l));
            sc[e] = s; ch[e] = s + bias[e];
        }
        bool used[NEXP];
#pragma unroll
        for (int e = 0; e < NEXP; e++) used[e] = false;
        int sel[TOPK]; float wsum = 0.f;
        for (int k = 0; k < TOPK; k++) {
            float best = -1e30f; int bi = 0;
            for (int e = 0; e < NEXP; e++)
                if (!used[e] && ch[e] > best) { best = ch[e]; bi = e; }
            used[bi] = true; sel[k] = bi; wsum += sc[bi];
        }
        float inv = RSCALE / wsum;
        for (int k = 0; k < TOPK; k++) {
            tw[t * TOPK + k] = sc[sel[k]] * inv;
            int pos = atomicAdd(&cnt[sel[k]], 1);
            list[sel[k] * T_TOK + pos] = t * TOPK + k;
        }
    }
}

// ---------------- cp.async fp16 MMA GEMM ----------------
// All operands fp16 in GMEM. 256 threads = 8 consumer warps (4M x 2N, 32x64).
// 4-stage cp.async pipeline; one __syncthreads per chunk (BK = 64 halfs).
#define BM 128
#define BROWS 128
#define TILE_HB 16384
#define STAGE_HB 32768
#define NSTAGE 4

template<bool FUSED>
__global__ void __launch_bounds__(256, 1)
mma_gemm(const __half* __restrict__ A,
         const __half* __restrict__ Bbase, long long bStride,
         void* __restrict__ Cv, int cStride, int upOff,
         int Mfixed, const int* __restrict__ cnt, int K,
         const int* __restrict__ list, int adiv)
{
    const int e = blockIdx.z;
    const int M = cnt ? cnt[e] : Mfixed;
    const int m0 = blockIdx.y * BM;
    if (m0 >= M) return;
    const int n0 = blockIdx.x;
    const __half* B = Bbase + (size_t)e * bStride;
    const int* lst = list ? (list + e * T_TOK) : nullptr;

    extern __shared__ char dynraw[];
    char* dyn = (char*)(((uintptr_t)dynraw + 1023) & ~(uintptr_t)1023);
    const uint32_t dynu = smem_u32(dyn);

    __shared__ int s_aOff[BM];
    __shared__ int s_cRow[BM];
    __shared__ int s_bRow[BROWS];

    const int tid = threadIdx.x;
    const int lane = tid & 31;
    const int warp = tid >> 5;

    if (tid < BM) {
        int r = m0 + tid; if (r > M - 1) r = M - 1;
        int pr = lst ? lst[r] : r;
        s_cRow[tid] = pr;
        s_aOff[tid] = (lst ? pr / adiv : pr) * K;
        int bj;
        if (FUSED) bj = (tid >> 1) + n0 * 64 + ((tid & 1) ? upOff : 0);
        else       bj = n0 * BROWS + tid;
        s_bRow[tid] = bj;
    }
    __syncthreads();

    // per-thread cp.async slots: 8 x 16B per chunk (4 A groups + 4 B groups)
    const __half* srcp[8];
    uint32_t dsto[8];
#pragma unroll
    for (int j = 0; j < 8; j++) {
        int g = (j & 3) * 256 + tid;     // 0..1023
        int row = g >> 3;                // 0..127
        int c16 = g & 7;                 // 16B group within 128B row
        bool isB = (j >= 4);
        srcp[j] = (isB ? (B + (size_t)s_bRow[row] * K)
                       : (A + (size_t)s_aOff[row])) + c16 * 8;
        dsto[j] = (isB ? (uint32_t)TILE_HB : 0u) +
                  (((uint32_t)(row * 128 + c16 * 16)) ^ ((uint32_t)(row & 7) << 4));
    }

    const int NC = K >> 6;

#define ISSUE(j) do {                                                     \
        uint32_t _sb = dynu + ((j) % NSTAGE) * STAGE_HB;                  \
        int _k0 = (j) << 6;                                               \
        _Pragma("unroll")                                                 \
        for (int t = 0; t < 8; t++)                                       \
            CP_ASYNC16(_sb + dsto[t], srcp[t] + _k0);                     \
        CP_COMMIT();                                                      \
    } while (0)

    // prologue: NSTAGE-1 chunks in flight
#pragma unroll
    for (int j = 0; j < NSTAGE - 1; j++)
        if (j < NC) ISSUE(j);

    // consumer layout: 4 warps along M, 2 along N; 32x64 per warp
    const int wm = warp & 3;
    const int wn = warp >> 2;
    const int aRow0 = wm * 32 + (lane & 7) + ((lane >> 3) & 1) * 8;
    const uint32_t aHi16 = ((lane >> 4) & 1) * 16;
    const uint32_t xorA = (uint32_t)(aRow0 & 7) << 4;
    const int bRow0 = wn * 64 + (lane & 7) + ((lane >> 4) & 1) * 8;
    const uint32_t bHi16 = ((lane >> 3) & 1) * 16;
    const uint32_t xorB = (uint32_t)(bRow0 & 7) << 4;

    float acc[2][8][4];
#pragma unroll
    for (int a = 0; a < 2; a++)
#pragma unroll
        for (int b = 0; b < 8; b++)
#pragma unroll
            for (int c = 0; c < 4; c++) acc[a][b][c] = 0.f;

    for (int i = 0; i < NC; i++) {
        CP_WAIT(NSTAGE - 2);          // chunk i landed
        __syncthreads();              // visible to all warps; stage (i-1)%NSTAGE free
        int nj = i + NSTAGE - 1;
        if (nj < NC) ISSUE(nj);

        const uint32_t su = dynu + (i % NSTAGE) * STAGE_HB;
#pragma unroll
        for (int ks = 0; ks < 4; ks++) {
            uint32_t aH[8];
#pragma unroll
            for (int g = 0; g < 2; g++) {
                uint32_t ao = su + (uint32_t)(aRow0 + g * 16) * 128 +
                              (((uint32_t)ks * 32 + aHi16) ^ xorA);
                LDSM4(&aH[g * 4], ao);
            }
#pragma unroll
            for (int nh = 0; nh < 2; nh++) {
                uint32_t bH[8];
#pragma unroll
                for (int q = 0; q < 2; q++) {
                    uint32_t bo = su + TILE_HB +
                                  (uint32_t)(bRow0 + nh * 32 + q * 16) * 128 +
                                  (((uint32_t)ks * 32 + bHi16) ^ xorB);
                    LDSM4(&bH[q * 4], bo);
                }
#pragma unroll
                for (int mi = 0; mi < 2; mi++)
#pragma unroll
                    for (int ni = 0; ni < 4; ni++)
                        mma_f16(acc[mi][nh * 4 + ni], &aH[mi * 4],
                                &bH[(ni >> 1) * 4 + (ni & 1) * 2]);
            }
        }
    }
#undef ISSUE

    // ---- epilogue ----
#pragma unroll
    for (int mi = 0; mi < 2; mi++) {
#pragma unroll
        for (int nt = 0; nt < 8; nt++) {
            const float* c = acc[mi][nt];
            int rl0 = wm * 32 + mi * 16 + (lane >> 2);
            int rl1 = rl0 + 8;
            if (FUSED) {
                __half* C = (__half*)Cv;
                int col = n0 * 64 + wn * 32 + nt * 4 + (lane & 3);
                if (m0 + rl0 < M)
                    C[(size_t)s_cRow[rl0] * cStride + col] = __float2half(silu_f(c[0]) * c[1]);
                if (m0 + rl1 < M)
                    C[(size_t)s_cRow[rl1] * cStride + col] = __float2half(silu_f(c[2]) * c[3]);
            } else {
                float* C = (float*)Cv;
                int col = n0 * BROWS + wn * 64 + nt * 8 + 2 * (lane & 3);
                if (m0 + rl0 < M) {
                    float2 o; o.x = c[0]; o.y = c[1];
                    *(float2*)(C + (size_t)s_cRow[rl0] * cStride + col) = o;
                }
                if (m0 + rl1 < M) {
                    float2 o; o.x = c[2]; o.y = c[3];
                    *(float2*)(C + (size_t)s_cRow[rl1] * cStride + col) = o;
                }
            }
        }
    }
}

// ---------------- combine ----------------
__global__ void combine_kernel(float* __restrict__ out,
                               const float* __restrict__ so,
                               const float* __restrict__ part,
                               const float* __restrict__ tw)
{
    int idx = blockIdx.x * blockDim.x + threadIdx.x;
    if (idx >= T_TOK * HID / 4) return;
    int t = idx / (HID / 4);
    int c = (idx % (HID / 4)) * 4;
    float4 acc = *(const float4*)(so + (size_t)t * HID + c);
#pragma unroll
    for (int s = 0; s < TOPK; s++) {
        float w = tw[t * TOPK + s];
        float4 pv = *(const float4*)(part + (size_t)(t * TOPK + s) * HID + c);
        acc.x = fmaf(w, pv.x, acc.x);
        acc.y = fmaf(w, pv.y, acc.y);
        acc.z = fmaf(w, pv.z, acc.z);
        acc.w = fmaf(w, pv.w, acc.w);
    }
    *(float4*)(out + (size_t)t * HID + c) = acc;
}

// ---------------- launch ----------------
extern "C" void kernel_launch(void* const* d_in, const int* in_sizes, int n_in,
                              void* d_out, int out_size)
{
    (void)in_sizes; (void)n_in; (void)out_size;
    const float* X    = (const float*)d_in[0];
    const float* gw   = (const float*)d_in[1];
    const float* bias = (const float*)d_in[2];
    const float* w1   = (const float*)d_in[3];
    const float* w2   = (const float*)d_in[4];
    const float* sw1  = (const float*)d_in[5];
    const float* sw2  = (const float*)d_in[6];
    float* out = (float*)d_out;

    __half *p_w1h, *p_w2h, *p_sw1h, *p_sw2h, *p_xh, *p_hbh, *p_hsh;
    float *p_part, *p_so, *p_tw;
    int *p_cnt, *p_list;
    cudaGetSymbolAddress((void**)&p_w1h,  g_w1h);
    cudaGetSymbolAddress((void**)&p_w2h,  g_w2h);
    cudaGetSymbolAddress((void**)&p_sw1h, g_sw1h);
    cudaGetSymbolAddress((void**)&p_sw2h, g_sw2h);
    cudaGetSymbolAddress((void**)&p_xh,   g_xh);
    cudaGetSymbolAddress((void**)&p_hbh,  g_hbh);
    cudaGetSymbolAddress((void**)&p_hsh,  g_hsh);
    cudaGetSymbolAddress((void**)&p_part, g_part);
    cudaGetSymbolAddress((void**)&p_so,   g_so);
    cudaGetSymbolAddress((void**)&p_tw,   g_tw);
    cudaGetSymbolAddress((void**)&p_cnt,  g_cnt);
    cudaGetSymbolAddress((void**)&p_list, g_list);

    const size_t dynsm = NSTAGE * STAGE_HB + 1024;
    cudaFuncSetAttribute(mma_gemm<true>,  cudaFuncAttributeMaxDynamicSharedMemorySize, (int)dynsm);
    cudaFuncSetAttribute(mma_gemm<false>, cudaFuncAttributeMaxDynamicSharedMemorySize, (int)dynsm);

    // 1. router (fp32 X)
    zero_cnt_kernel<<<1, 32>>>(p_cnt);
    router_kernel<<<T_TOK, 256>>>(X, gw, bias, p_cnt, p_list, p_tw);

    // 2. fp32 -> fp16 pre-conversion
    {
        int n4;
        n4 = (int)((size_t)T_TOK * HID / 4);
        cvt_f2h<<<(n4 + 255) / 256, 256>>>((const float4*)X, (uint2*)p_xh, n4);
        n4 = (int)((size_t)NEXP * 2 * IMID * HID / 4);
        cvt_f2h<<<(n4 + 255) / 256, 256>>>((const float4*)w1, (uint2*)p_w1h, n4);
        n4 = (int)((size_t)NEXP * HID * IMID / 4);
        cvt_f2h<<<(n4 + 255) / 256, 256>>>((const float4*)w2, (uint2*)p_w2h, n4);
        n4 = (int)((size_t)2 * ISH * HID / 4);
        cvt_f2h<<<(n4 + 255) / 256, 256>>>((const float4*)sw1, (uint2*)p_sw1h, n4);
        n4 = (int)((size_t)HID * ISH / 4);
        cvt_f2h<<<(n4 + 255) / 256, 256>>>((const float4*)sw2, (uint2*)p_sw2h, n4);
    }

    // 3. shared expert
    mma_gemm<true><<<dim3(ISH / 64, T_TOK / BM, 1), 256, dynsm>>>(
        p_xh, p_sw1h, 0, p_hsh, ISH, ISH, T_TOK, nullptr, HID, nullptr, 1);
    mma_gemm<false><<<dim3(HID / BROWS, T_TOK / BM, 1), 256, dynsm>>>(
        p_hsh, p_sw2h, 0, p_so, HID, 0, T_TOK, nullptr, ISH, nullptr, 1);

    // 4. routed experts
    mma_gemm<true><<<dim3(IMID / 64, 8, NEXP), 256, dynsm>>>(
        p_xh, p_w1h, (long long)(2 * IMID) * HID, p_hbh, IMID, IMID,
        0, p_cnt, HID, p_list, TOPK);
    mma_gemm<false><<<dim3(HID / BROWS, 8, NEXP), 256, dynsm>>>(
        p_hbh, p_w2h, (long long)HID * IMID, p_part, HID, 0,
        0, p_cnt, IMID, p_list, 1);

    // 5. combine
    combine_kernel<<<(T_TOK * HID / 4 + 255) / 256, 256>>>(out, p_so, p_part, p_tw);
}

// round 14
// speedup vs baseline: 2.0705x; 1.0245x over previous
#include <cuda_runtime.h>
#include <cuda_fp16.h>
#include <cstdint>
#include <math.h>

#define T_TOK 1024
#define HID   2048
#define IMID  1024
#define NEXP  16
#define TOPK  6
#define NPAIR (T_TOK * TOPK)
#define ISH   2048
#define RSCALE 2.5f

// ---------------- scratch ----------------
__device__ __half g_w1h [(size_t)NEXP * 2 * IMID * HID];
__device__ __half g_w2h [(size_t)NEXP * HID * IMID];
__device__ __half g_sw1h[(size_t)2 * ISH * HID];
__device__ __half g_sw2h[(size_t)HID * ISH];
__device__ __half g_xh  [(size_t)T_TOK * HID];
__device__ __half g_hbh [(size_t)NPAIR * IMID];
__device__ __half g_hsh [(size_t)T_TOK * ISH];
__device__ float  g_part[(size_t)NPAIR * HID];
__device__ float  g_so  [(size_t)T_TOK * HID];
__device__ int    g_cnt [NEXP];
__device__ int    g_list[NEXP * T_TOK];
__device__ float  g_tw  [T_TOK * TOPK];

// ---------------- helpers ----------------
__device__ __forceinline__ uint32_t smem_u32(const void* p) {
    uint32_t a;
    asm("{ .reg .u64 t; cvta.to.shared.u64 t, %1; cvt.u32.u64 %0, t; }" : "=r"(a) : "l"(p));
    return a;
}
__device__ __forceinline__ float silu_f(float x) { return x / (1.f + expf(-x)); }

#define LDSM4(r, addr) \
    asm volatile("ldmatrix.sync.aligned.m8n8.x4.shared.b16 {%0,%1,%2,%3}, [%4];" \
        : "=r"((r)[0]), "=r"((r)[1]), "=r"((r)[2]), "=r"((r)[3]) : "r"(addr))

__device__ __forceinline__ void mma_f16(float* c, const uint32_t* a, const uint32_t* b) {
    asm volatile(
        "mma.sync.aligned.m16n8k16.row.col.f32.f16.f16.f32 "
        "{%0,%1,%2,%3}, {%4,%5,%6,%7}, {%8,%9}, {%0,%1,%2,%3};"
        : "+f"(c[0]), "+f"(c[1]), "+f"(c[2]), "+f"(c[3])
        : "r"(a[0]), "r"(a[1]), "r"(a[2]), "r"(a[3]), "r"(b[0]), "r"(b[1]));
}

#define CP_ASYNC16(dst, src) \
    asm volatile("cp.async.cg.shared.global [%0], [%1], 16;" :: "r"(dst), "l"(src))
#define CP_COMMIT() asm volatile("cp.async.commit_group;" ::: "memory")
#define CP_WAIT(n)  asm volatile("cp.async.wait_group %0;" :: "n"(n) : "memory")

// ---------------- fp32 -> fp16 conversion ----------------
__global__ void __launch_bounds__(256)
cvt_f2h(const float4* __restrict__ src, uint2* __restrict__ dst, int n4)
{
    int i = blockIdx.x * 256 + threadIdx.x;
    if (i >= n4) return;
    float4 v = src[i];
    __half2 a = __floats2half2_rn(v.x, v.y);
    __half2 b = __floats2half2_rn(v.z, v.w);
    dst[i] = make_uint2(*(uint32_t*)&a, *(uint32_t*)&b);
}

// ---------------- router (also emits fp16 X) ----------------
__global__ void zero_cnt_kernel(int* cnt) { if (threadIdx.x < NEXP) cnt[threadIdx.x] = 0; }

__global__ void __launch_bounds__(256)
router_kernel(const float* __restrict__ X, const float* __restrict__ gw,
              const float* __restrict__ bias,
              int* __restrict__ cnt, int* __restrict__ list, float* __restrict__ tw,
              __half* __restrict__ xh)
{
    int t = blockIdx.x;
    __shared__ float red[NEXP * 256];
    float acc[NEXP];
#pragma unroll
    for (int e = 0; e < NEXP; e++) acc[e] = 0.f;
    const float* x = X + (size_t)t * HID;
    for (int h = threadIdx.x; h < HID; h += 256) {
        float xv = x[h];
        xh[(size_t)t * HID + h] = __float2half(xv);
#pragma unroll
        for (int e = 0; e < NEXP; e++) acc[e] += xv * gw[e * HID + h];
    }
#pragma unroll
    for (int e = 0; e < NEXP; e++) red[e * 256 + threadIdx.x] = acc[e];
    __syncthreads();
    for (int s = 128; s > 0; s >>= 1) {
        if (threadIdx.x < s) {
#pragma unroll
            for (int e = 0; e < NEXP; e++)
                red[e * 256 + threadIdx.x] += red[e * 256 + threadIdx.x + s];
        }
        __syncthreads();
    }
    if (threadIdx.x == 0) {
        float sc[NEXP], ch[NEXP];
#pragma unroll
        for (int e = 0; e < NEXP; e++) {
            float l = red[e * 256];
            float s = 1.f / (1.f + expf(-l));
            sc[e] = s; ch[e] = s + bias[e];
        }
        bool used[NEXP];
#pragma unroll
        for (int e = 0; e < NEXP; e++) used[e] = false;
        int sel[TOPK]; float wsum = 0.f;
        for (int k = 0; k < TOPK; k++) {
            float best = -1e30f; int bi = 0;
            for (int e = 0; e < NEXP; e++)
                if (!used[e] && ch[e] > best) { best = ch[e]; bi = e; }
            used[bi] = true; sel[k] = bi; wsum += sc[bi];
        }
        float inv = RSCALE / wsum;
        for (int k = 0; k < TOPK; k++) {
            tw[t * TOPK + k] = sc[sel[k]] * inv;
            int pos = atomicAdd(&cnt[sel[k]], 1);
            list[sel[k] * T_TOK + pos] = t * TOPK + k;
        }
    }
}

// ---------------- cp.async fp16 MMA GEMM, BK=128, frag double-buffer ----------------
// Stage (64 KB) = {A0, A1, B0, B1} 16 KB blocks (k-halves of 64 cols each).
// 256 threads = 8 consumer warps (4M x 2N, 32x64). 3-stage cp.async pipe.
#define BM 128
#define BROWS 128
#define BLK_HB 16384
#define STAGE_HB 65536
#define NSTAGE 3

template<bool FUSED>
__global__ void __launch_bounds__(256, 1)
mma_gemm(const __half* __restrict__ A,
         const __half* __restrict__ Bbase, long long bStride,
         void* __restrict__ Cv, int cStride, int upOff,
         int Mfixed, const int* __restrict__ cnt, int K,
         const int* __restrict__ list, int adiv)
{
    const int e = blockIdx.z;
    const int M = cnt ? cnt[e] : Mfixed;
    const int m0 = blockIdx.y * BM;
    if (m0 >= M) return;
    const int n0 = blockIdx.x;
    const __half* B = Bbase + (size_t)e * bStride;
    const int* lst = list ? (list + e * T_TOK) : nullptr;

    extern __shared__ char dynraw[];
    char* dyn = (char*)(((uintptr_t)dynraw + 1023) & ~(uintptr_t)1023);
    const uint32_t dynu = smem_u32(dyn);

    __shared__ int s_aOff[BM];
    __shared__ int s_cRow[BM];
    __shared__ int s_bRow[BROWS];

    const int tid = threadIdx.x;
    const int lane = tid & 31;
    const int warp = tid >> 5;

    if (tid < BM) {
        int r = m0 + tid; if (r > M - 1) r = M - 1;
        int pr = lst ? lst[r] : r;
        s_cRow[tid] = pr;
        s_aOff[tid] = (lst ? pr / adiv : pr) * K;
        int bj;
        if (FUSED) bj = (tid >> 1) + n0 * 64 + ((tid & 1) ? upOff : 0);
        else       bj = n0 * BROWS + tid;
        s_bRow[tid] = bj;
    }
    __syncthreads();

    // per-thread cp.async base slots (8): row + 16B-group; each slot issues 2 copies
    // per chunk (k-halves 0/1 at src +0/+64, dst +0/+BLK_HB).
    const __half* srcp[8];
    uint32_t dsto[8];
#pragma unroll
    for (int j = 0; j < 8; j++) {
        int g = (j & 3) * 256 + tid;     // 0..1023
        int row = g >> 3;                // 0..127
        int c16 = g & 7;                 // 16B group within 128B row
        bool isB = (j >= 4);
        srcp[j] = (isB ? (B + (size_t)s_bRow[row] * K)
                       : (A + (size_t)s_aOff[row])) + c16 * 8;
        dsto[j] = (isB ? 2u * BLK_HB : 0u) +
                  (((uint32_t)(row * 128 + c16 * 16)) ^ ((uint32_t)(row & 7) << 4));
    }

    const int NC = K >> 7;   // BK = 128

#define ISSUE(j) do {                                                     \
        uint32_t _sb = dynu + ((j) % NSTAGE) * STAGE_HB;                  \
        int _k0 = (j) << 7;                                               \
        _Pragma("unroll")                                                 \
        for (int t = 0; t < 8; t++) {                                     \
            CP_ASYNC16(_sb + dsto[t], srcp[t] + _k0);                     \
            CP_ASYNC16(_sb + dsto[t] + BLK_HB, srcp[t] + _k0 + 64);       \
        }                                                                 \
        CP_COMMIT();                                                      \
    } while (0)

    // prologue
#pragma unroll
    for (int j = 0; j < NSTAGE - 1; j++)
        if (j < NC) ISSUE(j);

    // consumer layout: 4 warps along M, 2 along N; 32x64 per warp
    const int wm = warp & 3;
    const int wn = warp >> 2;
    const int aRow0 = wm * 32 + (lane & 7) + ((lane >> 3) & 1) * 8;
    const uint32_t aHi16 = ((lane >> 4) & 1) * 16;
    const uint32_t xorA = (uint32_t)(aRow0 & 7) << 4;
    const int bRow0 = wn * 64 + (lane & 7) + ((lane >> 4) & 1) * 8;
    const uint32_t bHi16 = ((lane >> 3) & 1) * 16;
    const uint32_t xorB = (uint32_t)(bRow0 & 7) << 4;

    float acc[2][8][4];
#pragma unroll
    for (int a = 0; a < 2; a++)
#pragma unroll
        for (int b = 0; b < 8; b++)
#pragma unroll
            for (int c = 0; c < 4; c++) acc[a][b][c] = 0.f;

    uint32_t aF[2][8], bF[2][16];

    // load fragments for ks into buffer buf
#define LOADFRAG(ks, buf) do {                                                 \
        uint32_t _blk = su + ((ks) >> 2) * BLK_HB;                             \
        uint32_t _kc = (uint32_t)((ks) & 3) * 32;                              \
        _Pragma("unroll")                                                      \
        for (int g = 0; g < 2; g++) {                                          \
            uint32_t ao = _blk + (uint32_t)(aRow0 + g * 16) * 128 +            \
                          ((_kc + aHi16) ^ xorA);                              \
            LDSM4(&aF[buf][g * 4], ao);                                        \
        }                                                                      \
        _Pragma("unroll")                                                      \
        for (int nh = 0; nh < 2; nh++)                                         \
            _Pragma("unroll")                                                  \
            for (int q = 0; q < 2; q++) {                                      \
                uint32_t bo = _blk + 2u * BLK_HB +                             \
                              (uint32_t)(bRow0 + nh * 32 + q * 16) * 128 +     \
                              ((_kc + bHi16) ^ xorB);                          \
                LDSM4(&bF[buf][nh * 8 + q * 4], bo);                           \
            }                                                                  \
    } while (0)

#define DOMMA(buf) do {                                                        \
        _Pragma("unroll")                                                      \
        for (int nh = 0; nh < 2; nh++)                                         \
            _Pragma("unroll")                                                  \
            for (int mi = 0; mi < 2; mi++)                                     \
                _Pragma("unroll")                                              \
                for (int ni = 0; ni < 4; ni++)                                 \
                    mma_f16(acc[mi][nh * 4 + ni], &aF[buf][mi * 4],            \
                            &bF[buf][nh * 8 + (ni >> 1) * 4 + (ni & 1) * 2]);  \
    } while (0)

    for (int i = 0; i < NC; i++) {
        CP_WAIT(NSTAGE - 2);
        __syncthreads();
        int nj = i + NSTAGE - 1;
        if (nj < NC) ISSUE(nj);

        const uint32_t su = dynu + (i % NSTAGE) * STAGE_HB;
        LOADFRAG(0, 0);
#pragma unroll
        for (int ks = 0; ks < 8; ks++) {
            if (ks < 7) LOADFRAG(ks + 1, (ks + 1) & 1);
            DOMMA(ks & 1);
        }
    }
#undef ISSUE
#undef LOADFRAG
#undef DOMMA

    // ---- epilogue ----
#pragma unroll
    for (int mi = 0; mi < 2; mi++) {
#pragma unroll
        for (int nt = 0; nt < 8; nt++) {
            const float* c = acc[mi][nt];
            int rl0 = wm * 32 + mi * 16 + (lane >> 2);
            int rl1 = rl0 + 8;
            if (FUSED) {
                __half* C = (__half*)Cv;
                int col = n0 * 64 + wn * 32 + nt * 4 + (lane & 3);
                if (m0 + rl0 < M)
                    C[(size_t)s_cRow[rl0] * cStride + col] = __float2half(silu_f(c[0]) * c[1]);
                if (m0 + rl1 < M)
                    C[(size_t)s_cRow[rl1] * cStride + col] = __float2half(silu_f(c[2]) * c[3]);
            } else {
                float* C = (float*)Cv;
                int col = n0 * BROWS + wn * 64 + nt * 8 + 2 * (lane & 3);
                if (m0 + rl0 < M) {
                    float2 o; o.x = c[0]; o.y = c[1];
                    *(float2*)(C + (size_t)s_cRow[rl0] * cStride + col) = o;
                }
                if (m0 + rl1 < M) {
                    float2 o; o.x = c[2]; o.y = c[3];
                    *(float2*)(C + (size_t)s_cRow[rl1] * cStride + col) = o;
                }
            }
        }
    }
}

// ---------------- combine ----------------
__global__ void combine_kernel(float* __restrict__ out,
                               const float* __restrict__ so,
                               const float* __restrict__ part,
                               const float* __restrict__ tw)
{
    int idx = blockIdx.x * blockDim.x + threadIdx.x;
    if (idx >= T_TOK * HID / 4) return;
    int t = idx / (HID / 4);
    int c = (idx % (HID / 4)) * 4;
    float4 acc = *(const float4*)(so + (size_t)t * HID + c);
#pragma unroll
    for (int s = 0; s < TOPK; s++) {
        float w = tw[t * TOPK + s];
        float4 pv = *(const float4*)(part + (size_t)(t * TOPK + s) * HID + c);
        acc.x = fmaf(w, pv.x, acc.x);
        acc.y = fmaf(w, pv.y, acc.y);
        acc.z = fmaf(w, pv.z, acc.z);
        acc.w = fmaf(w, pv.w, acc.w);
    }
    *(float4*)(out + (size_t)t * HID + c) = acc;
}

// ---------------- launch ----------------
extern "C" void kernel_launch(void* const* d_in, const int* in_sizes, int n_in,
                              void* d_out, int out_size)
{
    (void)in_sizes; (void)n_in; (void)out_size;
    const float* X    = (const float*)d_in[0];
    const float* gw   = (const float*)d_in[1];
    const float* bias = (const float*)d_in[2];
    const float* w1   = (const float*)d_in[3];
    const float* w2   = (const float*)d_in[4];
    const float* sw1  = (const float*)d_in[5];
    const float* sw2  = (const float*)d_in[6];
    float* out = (float*)d_out;

    __half *p_w1h, *p_w2h, *p_sw1h, *p_sw2h, *p_xh, *p_hbh, *p_hsh;
    float *p_part, *p_so, *p_tw;
    int *p_cnt, *p_list;
    cudaGetSymbolAddress((void**)&p_w1h,  g_w1h);
    cudaGetSymbolAddress((void**)&p_w2h,  g_w2h);
    cudaGetSymbolAddress((void**)&p_sw1h, g_sw1h);
    cudaGetSymbolAddress((void**)&p_sw2h, g_sw2h);
    cudaGetSymbolAddress((void**)&p_xh,   g_xh);
    cudaGetSymbolAddress((void**)&p_hbh,  g_hbh);
    cudaGetSymbolAddress((void**)&p_hsh,  g_hsh);
    cudaGetSymbolAddress((void**)&p_part, g_part);
    cudaGetSymbolAddress((void**)&p_so,   g_so);
    cudaGetSymbolAddress((void**)&p_tw,   g_tw);
    cudaGetSymbolAddress((void**)&p_cnt,  g_cnt);
    cudaGetSymbolAddress((void**)&p_list, g_list);

    const size_t dynsm = NSTAGE * STAGE_HB + 1024;
    cudaFuncSetAttribute(mma_gemm<true>,  cudaFuncAttributeMaxDynamicSharedMemorySize, (int)dynsm);
    cudaFuncSetAttribute(mma_gemm<false>, cudaFuncAttributeMaxDynamicSharedMemorySize, (int)dynsm);

    // 1. router (+ X -> fp16)
    zero_cnt_kernel<<<1, 32>>>(p_cnt);
    router_kernel<<<T_TOK, 256>>>(X, gw, bias, p_cnt, p_list, p_tw, p_xh);

    // 2. weight fp32 -> fp16
    {
        int n4;
        n4 = (int)((size_t)2 * ISH * HID / 4);
        cvt_f2h<<<(n4 + 255) / 256, 256>>>((const float4*)sw1, (uint2*)p_sw1h, n4);
        n4 = (int)((size_t)HID * ISH / 4);
        cvt_f2h<<<(n4 + 255) / 256, 256>>>((const float4*)sw2, (uint2*)p_sw2h, n4);
        n4 = (int)((size_t)NEXP * 2 * IMID * HID / 4);
        cvt_f2h<<<(n4 + 255) / 256, 256>>>((const float4*)w1, (uint2*)p_w1h, n4);
        n4 = (int)((size_t)NEXP * HID * IMID / 4);
        cvt_f2h<<<(n4 + 255) / 256, 256>>>((const float4*)w2, (uint2*)p_w2h, n4);
    }

    // 3. shared expert
    mma_gemm<true><<<dim3(ISH / 64, T_TOK / BM, 1), 256, dynsm>>>(
        p_xh, p_sw1h, 0, p_hsh, ISH, ISH, T_TOK, nullptr, HID, nullptr, 1);
    mma_gemm<false><<<dim3(HID / BROWS, T_TOK / BM, 1), 256, dynsm>>>(
        p_hsh, p_sw2h, 0, p_so, HID, 0, T_TOK, nullptr, ISH, nullptr, 1);

    // 4. routed experts
    mma_gemm<true><<<dim3(IMID / 64, 8, NEXP), 256, dynsm>>>(
        p_xh, p_w1h, (long long)(2 * IMID) * HID, p_hbh, IMID, IMID,
        0, p_cnt, HID, p_list, TOPK);
    mma_gemm<false><<<dim3(HID / BROWS, 8, NEXP), 256, dynsm>>>(
        p_hbh, p_w2h, (long long)HID * IMID, p_part, HID, 0,
        0, p_cnt, IMID, p_list, 1);

    // 5. combine
    combine_kernel<<<(T_TOK * HID / 4 + 255) / 256, 256>>>(out, p_so, p_part, p_tw);
}